// round 1
// baseline (speedup 1.0000x reference)
#include <cuda_runtime.h>
#include <cstdint>

#define NROW 16384
#define DL 1024
#define DS 768
#define RK 64

// Scratch (allocation-free: __device__ globals)
__device__ __align__(16) float g_T1[3 * 64 * 768];   // B @ Ws^T
__device__ __align__(16) float g_C [3 * 64 * 64];    // T1 @ B^T
__device__ __align__(16) float g_D [3 * 1024 * 64];  // A @ C
__device__ __align__(16) float g_u [NROW * 192];     // x @ D

__device__ __forceinline__ uint32_t f2tf(float f) {
    uint32_t u;
    asm("cvt.rna.tf32.f32 %0, %1;" : "=r"(u) : "f"(f));
    return u;
}

__device__ __forceinline__ void mma8(float c[4], const uint32_t a[4], const uint32_t b[2]) {
    asm volatile(
        "mma.sync.aligned.m16n8k8.row.col.f32.tf32.tf32.f32 "
        "{%0,%1,%2,%3},{%4,%5,%6,%7},{%8,%9},{%0,%1,%2,%3};"
        : "+f"(c[0]), "+f"(c[1]), "+f"(c[2]), "+f"(c[3])
        : "r"(a[0]), "r"(a[1]), "r"(a[2]), "r"(a[3]), "r"(b[0]), "r"(b[1]));
}

// ---------------- precompute ----------------

__global__ void zero_k() {
    int i = blockIdx.x * blockDim.x + threadIdx.x;
    if (i < 3 * 64 * 768) g_T1[i] = 0.f;
    if (i < 3 * 64 * 64)  g_C[i]  = 0.f;
}

// T1[k][r][s] = sum_t B[k,r,t] * Ws[k,s,t]
// grid (6 s-blocks of 128, 8 t-splits of 96, 3 k), block 256
__global__ __launch_bounds__(256) void t1_k(const float* __restrict__ B,
                                            const float* __restrict__ Ws) {
    __shared__ float Bs[64][33];
    __shared__ float Wss[128][33];
    int k = blockIdx.z, s0 = blockIdx.x * 128, t0 = blockIdx.y * 96;
    int tid = threadIdx.x;
    const float* Bk = B  + k * 64 * 768;
    const float* Wk = Ws + k * 768 * 768;

    float acc[4][8];
#pragma unroll
    for (int i = 0; i < 4; i++)
#pragma unroll
        for (int j = 0; j < 8; j++) acc[i][j] = 0.f;

    int rl = tid >> 4;   // 0..15 (broadcast dim)
    int sl = tid & 15;   // 0..15 (stride-1 dim)

    for (int tc = 0; tc < 96; tc += 32) {
        int tb = t0 + tc;
        int c4 = (tid & 7) * 4;
#pragma unroll
        for (int p = 0; p < 2; p++) {
            int r = (tid >> 3) + p * 32;
            float4 v = *(const float4*)(Bk + r * 768 + tb + c4);
            Bs[r][c4] = v.x; Bs[r][c4 + 1] = v.y; Bs[r][c4 + 2] = v.z; Bs[r][c4 + 3] = v.w;
        }
#pragma unroll
        for (int p = 0; p < 4; p++) {
            int s = (tid >> 3) + p * 32;
            float4 v = *(const float4*)(Wk + (s0 + s) * 768 + tb + c4);
            Wss[s][c4] = v.x; Wss[s][c4 + 1] = v.y; Wss[s][c4 + 2] = v.z; Wss[s][c4 + 3] = v.w;
        }
        __syncthreads();
#pragma unroll 8
        for (int tt = 0; tt < 32; tt++) {
            float bv[4], wv[8];
#pragma unroll
            for (int i = 0; i < 4; i++) bv[i] = Bs[rl + 16 * i][tt];
#pragma unroll
            for (int j = 0; j < 8; j++) wv[j] = Wss[sl + 16 * j][tt];
#pragma unroll
            for (int i = 0; i < 4; i++)
#pragma unroll
                for (int j = 0; j < 8; j++) acc[i][j] += bv[i] * wv[j];
        }
        __syncthreads();
    }
#pragma unroll
    for (int i = 0; i < 4; i++)
#pragma unroll
        for (int j = 0; j < 8; j++)
            atomicAdd(&g_T1[(k * 64 + rl + 16 * i) * 768 + s0 + sl + 16 * j], acc[i][j]);
}

// C[k][r][r2] = sum_s T1[k,r,s] * B[k,r2,s]
// grid (8 s-splits of 96, 3 k), block 256
__global__ __launch_bounds__(256) void c_k(const float* __restrict__ B) {
    __shared__ float T1s[64][33];
    __shared__ float Bs2[64][33];
    int k = blockIdx.y, sb0 = blockIdx.x * 96;
    int tid = threadIdx.x;
    const float* Bk = B + k * 64 * 768;

    float acc[4][4];
#pragma unroll
    for (int i = 0; i < 4; i++)
#pragma unroll
        for (int j = 0; j < 4; j++) acc[i][j] = 0.f;

    int rl  = tid & 15;  // r: stride-1
    int r2l = tid >> 4;  // r2: broadcast

    for (int sc = 0; sc < 96; sc += 32) {
        int sb = sb0 + sc;
        int c4 = (tid & 7) * 4;
#pragma unroll
        for (int p = 0; p < 2; p++) {
            int r = (tid >> 3) + p * 32;
            float4 v = *(const float4*)(g_T1 + (k * 64 + r) * 768 + sb + c4);
            T1s[r][c4] = v.x; T1s[r][c4 + 1] = v.y; T1s[r][c4 + 2] = v.z; T1s[r][c4 + 3] = v.w;
            float4 w = *(const float4*)(Bk + r * 768 + sb + c4);
            Bs2[r][c4] = w.x; Bs2[r][c4 + 1] = w.y; Bs2[r][c4 + 2] = w.z; Bs2[r][c4 + 3] = w.w;
        }
        __syncthreads();
#pragma unroll 8
        for (int tt = 0; tt < 32; tt++) {
            float tv[4], bv[4];
#pragma unroll
            for (int i = 0; i < 4; i++) tv[i] = T1s[rl + 16 * i][tt];
#pragma unroll
            for (int j = 0; j < 4; j++) bv[j] = Bs2[r2l + 16 * j][tt];
#pragma unroll
            for (int i = 0; i < 4; i++)
#pragma unroll
                for (int j = 0; j < 4; j++) acc[i][j] += tv[i] * bv[j];
        }
        __syncthreads();
    }
#pragma unroll
    for (int i = 0; i < 4; i++)
#pragma unroll
        for (int j = 0; j < 4; j++)
            atomicAdd(&g_C[(k * 64 + rl + 16 * i) * 64 + r2l + 16 * j], acc[i][j]);
}

// D[k][d][r] = sum_r' A[k,d,r'] * C[k,r',r]
// grid (256 d-blocks of 4, 3 k), block 256
__global__ __launch_bounds__(256) void d_k(const float* __restrict__ A) {
    __shared__ float Cs[64][65];
    __shared__ float As[4][64];
    int k = blockIdx.y, d0 = blockIdx.x * 4;
    int tid = threadIdx.x;
    for (int idx = tid; idx < 4096; idx += 256)
        Cs[idx >> 6][idx & 63] = g_C[k * 4096 + idx];
    As[tid >> 6][tid & 63] = A[(k * 1024 + d0 + (tid >> 6)) * 64 + (tid & 63)];
    __syncthreads();
    int dl = tid >> 6, r = tid & 63;
    float acc = 0.f;
#pragma unroll
    for (int rp = 0; rp < 64; rp++) acc += As[dl][rp] * Cs[rp][r];
    g_D[(k * 1024 + d0 + dl) * 64 + r] = acc;
}

// ---------------- main GEMMs (tf32 mma.sync) ----------------

// S1: u[n, k*64+c] = sum_d x[n,d] * D[k,d,c]
// grid (128 row-tiles, 3 k), block 256 (8 warps -> 4x2 of 32x32 warp tiles)
__global__ __launch_bounds__(256) void s1_k(const float* __restrict__ x) {
    __shared__ float Xs[128][33];
    __shared__ float Dsh[32][65];
    int r0 = blockIdx.x * 128;
    int kh = blockIdx.y;
    int tid = threadIdx.x;
    int w = tid >> 5, lane = tid & 31, g = lane >> 2, tg = lane & 3;
    int wr = (w >> 1) * 32, wc = (w & 1) * 32;
    const float* Dk = g_D + kh * 1024 * 64;

    float acc[2][4][4];
#pragma unroll
    for (int mt = 0; mt < 2; mt++)
#pragma unroll
        for (int nt = 0; nt < 4; nt++)
#pragma unroll
            for (int q = 0; q < 4; q++) acc[mt][nt][q] = 0.f;

    for (int kc = 0; kc < 1024; kc += 32) {
        int c4 = (tid & 7) * 4;
#pragma unroll
        for (int p = 0; p < 4; p++) {
            int row = (tid >> 3) + p * 32;
            float4 v = *(const float4*)(x + (size_t)(r0 + row) * 1024 + kc + c4);
            Xs[row][c4] = v.x; Xs[row][c4 + 1] = v.y; Xs[row][c4 + 2] = v.z; Xs[row][c4 + 3] = v.w;
        }
        int c4b = (tid & 15) * 4;
#pragma unroll
        for (int p = 0; p < 2; p++) {
            int rr = (tid >> 4) + p * 16;
            float4 v = *(const float4*)(Dk + (size_t)(kc + rr) * 64 + c4b);
            Dsh[rr][c4b] = v.x; Dsh[rr][c4b + 1] = v.y; Dsh[rr][c4b + 2] = v.z; Dsh[rr][c4b + 3] = v.w;
        }
        __syncthreads();
#pragma unroll
        for (int kk = 0; kk < 32; kk += 8) {
            uint32_t a[2][4];
#pragma unroll
            for (int mt = 0; mt < 2; mt++) {
                int rb = wr + mt * 16;
                a[mt][0] = f2tf(Xs[rb + g][kk + tg]);
                a[mt][1] = f2tf(Xs[rb + g + 8][kk + tg]);
                a[mt][2] = f2tf(Xs[rb + g][kk + tg + 4]);
                a[mt][3] = f2tf(Xs[rb + g + 8][kk + tg + 4]);
            }
#pragma unroll
            for (int nt = 0; nt < 4; nt++) {
                uint32_t b[2];
                b[0] = f2tf(Dsh[kk + tg][wc + nt * 8 + g]);
                b[1] = f2tf(Dsh[kk + tg + 4][wc + nt * 8 + g]);
                mma8(acc[0][nt], a[0], b);
                mma8(acc[1][nt], a[1], b);
            }
        }
        __syncthreads();
    }
#pragma unroll
    for (int mt = 0; mt < 2; mt++) {
        int row = r0 + wr + mt * 16 + g;
#pragma unroll
        for (int nt = 0; nt < 4; nt++) {
            int col = kh * 64 + wc + nt * 8 + 2 * tg;
            *(float2*)(g_u + (size_t)row * 192 + col) =
                make_float2(acc[mt][nt][0], acc[mt][nt][1]);
            *(float2*)(g_u + (size_t)(row + 8) * 192 + col) =
                make_float2(acc[mt][nt][2], acc[mt][nt][3]);
        }
    }
}

// S2: out[n, k*1024 + e] = sum_r u[n, k*64+r] * A[k,e,r]
// grid (128 row-tiles, 16 e-tiles of 64, 3 k), block 256
__global__ __launch_bounds__(256) void s2_k(const float* __restrict__ A,
                                            float* __restrict__ out) {
    __shared__ float Us[128][33];
    __shared__ float Ash[64][33];
    int r0 = blockIdx.x * 128;
    int e0 = blockIdx.y * 64;
    int kh = blockIdx.z;
    int tid = threadIdx.x;
    int w = tid >> 5, lane = tid & 31, g = lane >> 2, tg = lane & 3;
    int wr = (w >> 1) * 32, wc = (w & 1) * 32;

    float acc[2][4][4];
#pragma unroll
    for (int mt = 0; mt < 2; mt++)
#pragma unroll
        for (int nt = 0; nt < 4; nt++)
#pragma unroll
            for (int q = 0; q < 4; q++) acc[mt][nt][q] = 0.f;

    for (int kc = 0; kc < 64; kc += 32) {
        int c4 = (tid & 7) * 4;
#pragma unroll
        for (int p = 0; p < 4; p++) {
            int row = (tid >> 3) + p * 32;
            float4 v = *(const float4*)(g_u + (size_t)(r0 + row) * 192 + kh * 64 + kc + c4);
            Us[row][c4] = v.x; Us[row][c4 + 1] = v.y; Us[row][c4 + 2] = v.z; Us[row][c4 + 3] = v.w;
        }
#pragma unroll
        for (int p = 0; p < 2; p++) {
            int e = (tid >> 3) + p * 32;
            float4 v = *(const float4*)(A + (size_t)(kh * 1024 + e0 + e) * 64 + kc + c4);
            Ash[e][c4] = v.x; Ash[e][c4 + 1] = v.y; Ash[e][c4 + 2] = v.z; Ash[e][c4 + 3] = v.w;
        }
        __syncthreads();
#pragma unroll
        for (int kk = 0; kk < 32; kk += 8) {
            uint32_t a[2][4];
#pragma unroll
            for (int mt = 0; mt < 2; mt++) {
                int rb = wr + mt * 16;
                a[mt][0] = f2tf(Us[rb + g][kk + tg]);
                a[mt][1] = f2tf(Us[rb + g + 8][kk + tg]);
                a[mt][2] = f2tf(Us[rb + g][kk + tg + 4]);
                a[mt][3] = f2tf(Us[rb + g + 8][kk + tg + 4]);
            }
#pragma unroll
            for (int nt = 0; nt < 4; nt++) {
                uint32_t b[2];
                b[0] = f2tf(Ash[wc + nt * 8 + g][kk + tg]);
                b[1] = f2tf(Ash[wc + nt * 8 + g][kk + tg + 4]);
                mma8(acc[0][nt], a[0], b);
                mma8(acc[1][nt], a[1], b);
            }
        }
        __syncthreads();
    }
#pragma unroll
    for (int mt = 0; mt < 2; mt++) {
        int row = r0 + wr + mt * 16 + g;
#pragma unroll
        for (int nt = 0; nt < 4; nt++) {
            int col = kh * 1024 + e0 + wc + nt * 8 + 2 * tg;
            *(float2*)(out + (size_t)row * 3072 + col) =
                make_float2(acc[mt][nt][0], acc[mt][nt][1]);
            *(float2*)(out + (size_t)(row + 8) * 3072 + col) =
                make_float2(acc[mt][nt][2], acc[mt][nt][3]);
        }
    }
}

extern "C" void kernel_launch(void* const* d_in, const int* in_sizes, int n_in,
                              void* d_out, int out_size) {
    (void)in_sizes; (void)n_in; (void)out_size;
    const float* x  = (const float*)d_in[0];
    const float* Ws = (const float*)d_in[1];
    const float* A  = (const float*)d_in[2];
    const float* B  = (const float*)d_in[3];
    float* out = (float*)d_out;

    zero_k<<<576, 256>>>();
    t1_k<<<dim3(6, 8, 3), 256>>>(B, Ws);
    c_k<<<dim3(8, 3), 256>>>(B);
    d_k<<<dim3(256, 3), 256>>>(A);
    s1_k<<<dim3(128, 3), 256>>>(x);
    s2_k<<<dim3(128, 16, 3), 256>>>(A, out);
}

// round 2
// speedup vs baseline: 1.2980x; 1.2980x over previous
#include <cuda_runtime.h>
#include <cstdint>

#define NROW 16384

// Scratch (allocation-free: __device__ globals)
__device__ __align__(16) float g_T1[3 * 64 * 768];   // B @ Ws^T
__device__ __align__(16) float g_C [3 * 64 * 64];    // T1 @ B^T
__device__ __align__(16) float g_D [3 * 1024 * 64];  // A @ C

__device__ __forceinline__ uint32_t f2tf(float f) {
    uint32_t u;
    asm("cvt.rna.tf32.f32 %0, %1;" : "=r"(u) : "f"(f));
    return u;
}

__device__ __forceinline__ void mma8(float c[4], const uint32_t a[4], const uint32_t b[2]) {
    asm volatile(
        "mma.sync.aligned.m16n8k8.row.col.f32.tf32.tf32.f32 "
        "{%0,%1,%2,%3},{%4,%5,%6,%7},{%8,%9},{%0,%1,%2,%3};"
        : "+f"(c[0]), "+f"(c[1]), "+f"(c[2]), "+f"(c[3])
        : "r"(a[0]), "r"(a[1]), "r"(a[2]), "r"(a[3]), "r"(b[0]), "r"(b[1]));
}

// ---------------- precompute ----------------

__global__ void zero_k() {
    int i = blockIdx.x * blockDim.x + threadIdx.x;
    if (i < 3 * 64 * 768) g_T1[i] = 0.f;
    if (i < 3 * 64 * 64)  g_C[i]  = 0.f;
}

// T1[k][r][s] = sum_t B[k,r,t] * Ws[k,s,t]
__global__ __launch_bounds__(256) void t1_k(const float* __restrict__ B,
                                            const float* __restrict__ Ws) {
    __shared__ float Bs[64][33];
    __shared__ float Wss[128][33];
    int k = blockIdx.z, s0 = blockIdx.x * 128, t0 = blockIdx.y * 96;
    int tid = threadIdx.x;
    const float* Bk = B  + k * 64 * 768;
    const float* Wk = Ws + k * 768 * 768;

    float acc[4][8];
#pragma unroll
    for (int i = 0; i < 4; i++)
#pragma unroll
        for (int j = 0; j < 8; j++) acc[i][j] = 0.f;

    int rl = tid >> 4;
    int sl = tid & 15;

    for (int tc = 0; tc < 96; tc += 32) {
        int tb = t0 + tc;
        int c4 = (tid & 7) * 4;
#pragma unroll
        for (int p = 0; p < 2; p++) {
            int r = (tid >> 3) + p * 32;
            float4 v = *(const float4*)(Bk + r * 768 + tb + c4);
            Bs[r][c4] = v.x; Bs[r][c4 + 1] = v.y; Bs[r][c4 + 2] = v.z; Bs[r][c4 + 3] = v.w;
        }
#pragma unroll
        for (int p = 0; p < 4; p++) {
            int s = (tid >> 3) + p * 32;
            float4 v = *(const float4*)(Wk + (s0 + s) * 768 + tb + c4);
            Wss[s][c4] = v.x; Wss[s][c4 + 1] = v.y; Wss[s][c4 + 2] = v.z; Wss[s][c4 + 3] = v.w;
        }
        __syncthreads();
#pragma unroll 8
        for (int tt = 0; tt < 32; tt++) {
            float bv[4], wv[8];
#pragma unroll
            for (int i = 0; i < 4; i++) bv[i] = Bs[rl + 16 * i][tt];
#pragma unroll
            for (int j = 0; j < 8; j++) wv[j] = Wss[sl + 16 * j][tt];
#pragma unroll
            for (int i = 0; i < 4; i++)
#pragma unroll
                for (int j = 0; j < 8; j++) acc[i][j] += bv[i] * wv[j];
        }
        __syncthreads();
    }
#pragma unroll
    for (int i = 0; i < 4; i++)
#pragma unroll
        for (int j = 0; j < 8; j++)
            atomicAdd(&g_T1[(k * 64 + rl + 16 * i) * 768 + s0 + sl + 16 * j], acc[i][j]);
}

// C[k][r][r2] = sum_s T1[k,r,s] * B[k,r2,s]
__global__ __launch_bounds__(256) void c_k(const float* __restrict__ B) {
    __shared__ float T1s[64][33];
    __shared__ float Bs2[64][33];
    int k = blockIdx.y, sb0 = blockIdx.x * 96;
    int tid = threadIdx.x;
    const float* Bk = B + k * 64 * 768;

    float acc[4][4];
#pragma unroll
    for (int i = 0; i < 4; i++)
#pragma unroll
        for (int j = 0; j < 4; j++) acc[i][j] = 0.f;

    int rl  = tid & 15;
    int r2l = tid >> 4;

    for (int sc = 0; sc < 96; sc += 32) {
        int sb = sb0 + sc;
        int c4 = (tid & 7) * 4;
#pragma unroll
        for (int p = 0; p < 2; p++) {
            int r = (tid >> 3) + p * 32;
            float4 v = *(const float4*)(g_T1 + (k * 64 + r) * 768 + sb + c4);
            T1s[r][c4] = v.x; T1s[r][c4 + 1] = v.y; T1s[r][c4 + 2] = v.z; T1s[r][c4 + 3] = v.w;
            float4 w = *(const float4*)(Bk + r * 768 + sb + c4);
            Bs2[r][c4] = w.x; Bs2[r][c4 + 1] = w.y; Bs2[r][c4 + 2] = w.z; Bs2[r][c4 + 3] = w.w;
        }
        __syncthreads();
#pragma unroll 8
        for (int tt = 0; tt < 32; tt++) {
            float tv[4], bv[4];
#pragma unroll
            for (int i = 0; i < 4; i++) tv[i] = T1s[rl + 16 * i][tt];
#pragma unroll
            for (int j = 0; j < 4; j++) bv[j] = Bs2[r2l + 16 * j][tt];
#pragma unroll
            for (int i = 0; i < 4; i++)
#pragma unroll
                for (int j = 0; j < 4; j++) acc[i][j] += tv[i] * bv[j];
        }
        __syncthreads();
    }
#pragma unroll
    for (int i = 0; i < 4; i++)
#pragma unroll
        for (int j = 0; j < 4; j++)
            atomicAdd(&g_C[(k * 64 + rl + 16 * i) * 64 + r2l + 16 * j], acc[i][j]);
}

// D[k][d][r] = sum_r' A[k,d,r'] * C[k,r',r]   grid (32, 3), block 256
__global__ __launch_bounds__(256) void d_k2(const float* __restrict__ A) {
    __shared__ float Cs[64][68];
    __shared__ float As[32][65];
    int k = blockIdx.y, d0 = blockIdx.x * 32;
    int tid = threadIdx.x;
    for (int idx = tid; idx < 4096; idx += 256)
        Cs[idx >> 6][idx & 63] = g_C[k * 4096 + idx];
    for (int idx = tid; idx < 2048; idx += 256)
        As[idx >> 6][idx & 63] = A[(size_t)(k * 1024 + d0 + (idx >> 6)) * 64 + (idx & 63)];
    __syncthreads();
    int dl = tid >> 3, rq = (tid & 7) * 8;
    float acc[8];
#pragma unroll
    for (int i = 0; i < 8; i++) acc[i] = 0.f;
    for (int rp = 0; rp < 64; rp++) {
        float av = As[dl][rp];
        float4 c0 = *(const float4*)&Cs[rp][rq];
        float4 c1 = *(const float4*)&Cs[rp][rq + 4];
        acc[0] += av * c0.x; acc[1] += av * c0.y;
        acc[2] += av * c0.z; acc[3] += av * c0.w;
        acc[4] += av * c1.x; acc[5] += av * c1.y;
        acc[6] += av * c1.z; acc[7] += av * c1.w;
    }
#pragma unroll
    for (int i = 0; i < 8; i++)
        g_D[(size_t)(k * 1024 + d0 + dl) * 64 + rq + i] = acc[i];
}

// ---------------- fused main GEMM: out = (x @ D) @ A^T ----------------
// Fragment-major tf32 smem layouts:
//   A-operand: sA[((rt*8+ks)*32 + (lane^(ks&3)))*4 + f],  f = q*2 + h  -> LDS.128
//   B-operand: sB[((ct*8+ks)*32 + (lane^(ks&3)))*2 + q]               -> LDS.64
// grid (3, 128): kh = blockIdx.x, row tile = blockIdx.y*128
__global__ __launch_bounds__(256, 2) void fused_k(const float* __restrict__ x,
                                                  const float* __restrict__ A,
                                                  float* __restrict__ out) {
    __shared__ uint32_t sA[8 * 8 * 32 * 4];   // 32 KB
    __shared__ uint32_t sB[8 * 8 * 32 * 2];   // 16 KB

    const int kh = blockIdx.x;
    const int r0 = blockIdx.y * 128;
    const int tid = threadIdx.x;
    const int w = tid >> 5, lane = tid & 31;
    const int gp = lane >> 2, tgp = lane & 3;
    const int wr = (w >> 1) * 32, wc = (w & 1) * 32;
    const float* Dk = g_D + kh * 1024 * 64;
    const float* Ak = A + (size_t)kh * 1024 * 64;

    float acc[2][4][4];
#pragma unroll
    for (int mt = 0; mt < 2; mt++)
#pragma unroll
        for (int nt = 0; nt < 4; nt++)
#pragma unroll
            for (int i = 0; i < 4; i++) acc[mt][nt][i] = 0.f;

    // ---- Phase 1: u[128][64] = x_tile @ D ----
    for (int kc = 0; kc < 1024; kc += 64) {
        // stage X chunk (128 rows x 64 depth), convert to tf32, frag-major
#pragma unroll
        for (int p = 0; p < 8; p++) {
            int row = (tid >> 4) + p * 16;
            int rt = row >> 4, h = (row >> 3) & 1, g = row & 7;
            int c4 = (tid & 15) * 4;
            int ks = c4 >> 3, q = (c4 >> 2) & 1, sw = ks & 3;
            float4 v = *(const float4*)(x + (size_t)(r0 + row) * 1024 + kc + c4);
            int base = ((rt * 8 + ks) * 32) * 4 + (q * 2 + h);
            int l0 = g * 4;
            sA[base + (l0 + (0 ^ sw)) * 4] = f2tf(v.x);
            sA[base + (l0 + (1 ^ sw)) * 4] = f2tf(v.y);
            sA[base + (l0 + (2 ^ sw)) * 4] = f2tf(v.z);
            sA[base + (l0 + (3 ^ sw)) * 4] = f2tf(v.w);
        }
        // stage D chunk (64 depth x 64 cols)
#pragma unroll
        for (int p = 0; p < 4; p++) {
            int rr = (tid >> 4) + p * 16;     // k-row within chunk
            int ks = rr >> 3, tg = rr & 3, q = (rr >> 2) & 1;
            int c4 = (tid & 15) * 4;
            float4 v = *(const float4*)(Dk + (size_t)(kc + rr) * 64 + c4);
            float vv[4] = {v.x, v.y, v.z, v.w};
#pragma unroll
            for (int j = 0; j < 4; j++) {
                int col = c4 + j, ct = col >> 3, gc = col & 7;
                int lsw = (gc * 4 + tg) ^ (ks & 3);
                sB[((ct * 8 + ks) * 32 + lsw) * 2 + q] = f2tf(vv[j]);
            }
        }
        __syncthreads();
#pragma unroll
        for (int ks = 0; ks < 8; ks++) {
            int lsw = lane ^ (ks & 3);
            uint32_t a0[4], a1[4];
            *(uint4*)a0 = *(const uint4*)&sA[(((2 * (w >> 1)) * 8 + ks) * 32 + lsw) * 4];
            *(uint4*)a1 = *(const uint4*)&sA[(((2 * (w >> 1) + 1) * 8 + ks) * 32 + lsw) * 4];
#pragma unroll
            for (int nt = 0; nt < 4; nt++) {
                uint32_t b[2];
                *(uint2*)b = *(const uint2*)&sB[((((w & 1) * 4 + nt) * 8 + ks) * 32 + lsw) * 2];
                mma8(acc[0][nt], a0, b);
                mma8(acc[1][nt], a1, b);
            }
        }
        __syncthreads();
    }

    // ---- spill u to smem as phase-2 A operand (tf32, frag-major) ----
#pragma unroll
    for (int mt = 0; mt < 2; mt++) {
        int rt = 2 * (w >> 1) + mt;
#pragma unroll
        for (int nt = 0; nt < 4; nt++) {
            int ks2 = (w & 1) * 4 + nt;
            int sw = ks2 & 3;
#pragma unroll
            for (int i = 0; i < 4; i++) {
                int rcol = 2 * tgp + (i & 1);
                int lane2 = (gp * 4 + (rcol & 3)) ^ sw;
                int f = (rcol >> 2) * 2 + (i >> 1);
                sA[((rt * 8 + ks2) * 32 + lane2) * 4 + f] = f2tf(acc[mt][nt][i]);
            }
        }
    }
    __syncthreads();

    // ---- Phase 2: out_tile = u @ A^T, 16 e-tiles of 64 ----
    for (int et = 0; et < 16; et++) {
        int e0 = et * 64;
        // stage A chunk (64 e-rows x 64 r) into sB
#pragma unroll
        for (int p = 0; p < 4; p++) {
            int er = (tid >> 4) + p * 16;
            int ct = er >> 3, gc = er & 7;
            int c4 = (tid & 15) * 4;
            int ks = c4 >> 3, q = (c4 >> 2) & 1, sw = ks & 3;
            float4 v = *(const float4*)(Ak + (size_t)(e0 + er) * 64 + c4);
            sB[((ct * 8 + ks) * 32 + ((gc * 4 + 0) ^ sw)) * 2 + q] = f2tf(v.x);
            sB[((ct * 8 + ks) * 32 + ((gc * 4 + 1) ^ sw)) * 2 + q] = f2tf(v.y);
            sB[((ct * 8 + ks) * 32 + ((gc * 4 + 2) ^ sw)) * 2 + q] = f2tf(v.z);
            sB[((ct * 8 + ks) * 32 + ((gc * 4 + 3) ^ sw)) * 2 + q] = f2tf(v.w);
        }
        __syncthreads();

        float o[2][4][4];
#pragma unroll
        for (int mt = 0; mt < 2; mt++)
#pragma unroll
            for (int nt = 0; nt < 4; nt++)
#pragma unroll
                for (int i = 0; i < 4; i++) o[mt][nt][i] = 0.f;

#pragma unroll
        for (int ks = 0; ks < 8; ks++) {
            int lsw = lane ^ (ks & 3);
            uint32_t a0[4], a1[4];
            *(uint4*)a0 = *(const uint4*)&sA[(((2 * (w >> 1)) * 8 + ks) * 32 + lsw) * 4];
            *(uint4*)a1 = *(const uint4*)&sA[(((2 * (w >> 1) + 1) * 8 + ks) * 32 + lsw) * 4];
#pragma unroll
            for (int nt = 0; nt < 4; nt++) {
                uint32_t b[2];
                *(uint2*)b = *(const uint2*)&sB[((((w & 1) * 4 + nt) * 8 + ks) * 32 + lsw) * 2];
                mma8(o[0][nt], a0, b);
                mma8(o[1][nt], a1, b);
            }
        }

#pragma unroll
        for (int mt = 0; mt < 2; mt++) {
            int row = r0 + wr + mt * 16 + gp;
#pragma unroll
            for (int nt = 0; nt < 4; nt++) {
                size_t col = (size_t)kh * 1024 + e0 + wc + nt * 8 + 2 * tgp;
                *(float2*)(out + (size_t)row * 3072 + col) =
                    make_float2(o[mt][nt][0], o[mt][nt][1]);
                *(float2*)(out + (size_t)(row + 8) * 3072 + col) =
                    make_float2(o[mt][nt][2], o[mt][nt][3]);
            }
        }
        __syncthreads();
    }
}

extern "C" void kernel_launch(void* const* d_in, const int* in_sizes, int n_in,
                              void* d_out, int out_size) {
    (void)in_sizes; (void)n_in; (void)out_size;
    const float* x  = (const float*)d_in[0];
    const float* Ws = (const float*)d_in[1];
    const float* A  = (const float*)d_in[2];
    const float* B  = (const float*)d_in[3];
    float* out = (float*)d_out;

    zero_k<<<576, 256>>>();
    t1_k<<<dim3(6, 8, 3), 256>>>(B, Ws);
    c_k<<<dim3(8, 3), 256>>>(B);
    d_k2<<<dim3(32, 3), 256>>>(A);
    fused_k<<<dim3(3, 128), 256>>>(x, A, out);
}

// round 3
// speedup vs baseline: 1.4105x; 1.0867x over previous
#include <cuda_runtime.h>
#include <cstdint>

#define NROW 16384

// Scratch (allocation-free: __device__ globals)
__device__ __align__(16) float g_T1[3 * 64 * 768];   // B @ Ws^T
__device__ __align__(16) float g_C [3 * 64 * 64];    // T1 @ B^T
__device__ __align__(16) float g_D [3 * 1024 * 64];  // A @ C

__device__ __forceinline__ uint32_t f2tf(float f) {
    uint32_t u;
    asm("cvt.rna.tf32.f32 %0, %1;" : "=r"(u) : "f"(f));
    return u;
}

__device__ __forceinline__ void mma8(float c[4], const uint32_t a[4], const uint32_t b[2]) {
    asm volatile(
        "mma.sync.aligned.m16n8k8.row.col.f32.tf32.tf32.f32 "
        "{%0,%1,%2,%3},{%4,%5,%6,%7},{%8,%9},{%0,%1,%2,%3};"
        : "+f"(c[0]), "+f"(c[1]), "+f"(c[2]), "+f"(c[3])
        : "r"(a[0]), "r"(a[1]), "r"(a[2]), "r"(a[3]), "r"(b[0]), "r"(b[1]));
}

// ---------------- precompute ----------------

__global__ void zero_k() {
    int i = blockIdx.x * blockDim.x + threadIdx.x;
    if (i < 3 * 64 * 768) g_T1[i] = 0.f;
    if (i < 3 * 64 * 64)  g_C[i]  = 0.f;
}

// T1[k][r][s] = sum_t B[k,r,t] * Ws[k,s,t]
// grid (6 s-blocks of 128, 12 t-splits of 64, 3 k), block 256
__global__ __launch_bounds__(256) void t1_k(const float* __restrict__ B,
                                            const float* __restrict__ Ws) {
    __shared__ float Bs[64][33];
    __shared__ float Wss[128][33];
    int k = blockIdx.z, s0 = blockIdx.x * 128, t0 = blockIdx.y * 64;
    int tid = threadIdx.x;
    const float* Bk = B  + k * 64 * 768;
    const float* Wk = Ws + k * 768 * 768;

    float acc[4][8];
#pragma unroll
    for (int i = 0; i < 4; i++)
#pragma unroll
        for (int j = 0; j < 8; j++) acc[i][j] = 0.f;

    int rl = tid >> 4;
    int sl = tid & 15;

    for (int tc = 0; tc < 64; tc += 32) {
        int tb = t0 + tc;
        int c4 = (tid & 7) * 4;
#pragma unroll
        for (int p = 0; p < 2; p++) {
            int r = (tid >> 3) + p * 32;
            float4 v = *(const float4*)(Bk + r * 768 + tb + c4);
            Bs[r][c4] = v.x; Bs[r][c4 + 1] = v.y; Bs[r][c4 + 2] = v.z; Bs[r][c4 + 3] = v.w;
        }
#pragma unroll
        for (int p = 0; p < 4; p++) {
            int s = (tid >> 3) + p * 32;
            float4 v = *(const float4*)(Wk + (s0 + s) * 768 + tb + c4);
            Wss[s][c4] = v.x; Wss[s][c4 + 1] = v.y; Wss[s][c4 + 2] = v.z; Wss[s][c4 + 3] = v.w;
        }
        __syncthreads();
#pragma unroll 8
        for (int tt = 0; tt < 32; tt++) {
            float bv[4], wv[8];
#pragma unroll
            for (int i = 0; i < 4; i++) bv[i] = Bs[rl + 16 * i][tt];
#pragma unroll
            for (int j = 0; j < 8; j++) wv[j] = Wss[sl + 16 * j][tt];
#pragma unroll
            for (int i = 0; i < 4; i++)
#pragma unroll
                for (int j = 0; j < 8; j++) acc[i][j] += bv[i] * wv[j];
        }
        __syncthreads();
    }
#pragma unroll
    for (int i = 0; i < 4; i++)
#pragma unroll
        for (int j = 0; j < 8; j++)
            atomicAdd(&g_T1[(k * 64 + rl + 16 * i) * 768 + s0 + sl + 16 * j], acc[i][j]);
}

// C[k][r][r2] = sum_s T1[k,r,s] * B[k,r2,s]
__global__ __launch_bounds__(256) void c_k(const float* __restrict__ B) {
    __shared__ float T1s[64][33];
    __shared__ float Bs2[64][33];
    int k = blockIdx.y, sb0 = blockIdx.x * 96;
    int tid = threadIdx.x;
    const float* Bk = B + k * 64 * 768;

    float acc[4][4];
#pragma unroll
    for (int i = 0; i < 4; i++)
#pragma unroll
        for (int j = 0; j < 4; j++) acc[i][j] = 0.f;

    int rl  = tid & 15;
    int r2l = tid >> 4;

    for (int sc = 0; sc < 96; sc += 32) {
        int sb = sb0 + sc;
        int c4 = (tid & 7) * 4;
#pragma unroll
        for (int p = 0; p < 2; p++) {
            int r = (tid >> 3) + p * 32;
            float4 v = *(const float4*)(g_T1 + (k * 64 + r) * 768 + sb + c4);
            T1s[r][c4] = v.x; T1s[r][c4 + 1] = v.y; T1s[r][c4 + 2] = v.z; T1s[r][c4 + 3] = v.w;
            float4 w = *(const float4*)(Bk + r * 768 + sb + c4);
            Bs2[r][c4] = w.x; Bs2[r][c4 + 1] = w.y; Bs2[r][c4 + 2] = w.z; Bs2[r][c4 + 3] = w.w;
        }
        __syncthreads();
#pragma unroll 8
        for (int tt = 0; tt < 32; tt++) {
            float tv[4], bv[4];
#pragma unroll
            for (int i = 0; i < 4; i++) tv[i] = T1s[rl + 16 * i][tt];
#pragma unroll
            for (int j = 0; j < 4; j++) bv[j] = Bs2[r2l + 16 * j][tt];
#pragma unroll
            for (int i = 0; i < 4; i++)
#pragma unroll
                for (int j = 0; j < 4; j++) acc[i][j] += tv[i] * bv[j];
        }
        __syncthreads();
    }
#pragma unroll
    for (int i = 0; i < 4; i++)
#pragma unroll
        for (int j = 0; j < 4; j++)
            atomicAdd(&g_C[(k * 64 + rl + 16 * i) * 64 + r2l + 16 * j], acc[i][j]);
}

// D[k][d][r] = sum_r' A[k,d,r'] * C[k,r',r]
// grid (128 d-blocks of 8, 3 k), block 256 (8 rows x 32 threads, 2 outputs each)
__global__ __launch_bounds__(256) void d_k3(const float* __restrict__ A) {
    __shared__ float Cs[64][66];
    __shared__ float As[8][64];
    int k = blockIdx.y, d0 = blockIdx.x * 8;
    int tid = threadIdx.x;
    for (int idx = tid; idx < 4096; idx += 256)
        Cs[idx >> 6][idx & 63] = g_C[k * 4096 + idx];
    for (int idx = tid; idx < 512; idx += 256)
        As[idx >> 6][idx & 63] = A[(size_t)(k * 1024 + d0 + (idx >> 6)) * 64 + (idx & 63)];
    __syncthreads();
    int dl = tid >> 5, r = (tid & 31) * 2;
    float a0 = 0.f, a1 = 0.f;
#pragma unroll
    for (int rp = 0; rp < 64; rp++) {
        float av = As[dl][rp];
        float2 c = *(const float2*)&Cs[rp][r];
        a0 += av * c.x; a1 += av * c.y;
    }
    *(float2*)(g_D + (size_t)(k * 1024 + d0 + dl) * 64 + r) = make_float2(a0, a1);
}

// ---------------- fused main GEMM: out = (x @ D) @ A^T ----------------
// Fragment-major tf32 smem layouts:
//   A-operand: sA[((rt*8+ks)*32 + (lane^(ks&3)))*4 + f],  f = q*2 + h  -> LDS.128
//   B-operand: sB[((ct*8+ks)*32 + (lane^(ks&3)))*2 + q]               -> LDS.64
// grid (3, 128), block 256; software-pipelined global->reg prefetch.
__global__ __launch_bounds__(256, 2) void fused_k(const float* __restrict__ x,
                                                  const float* __restrict__ A,
                                                  float* __restrict__ out) {
    __shared__ uint32_t sA[8 * 8 * 32 * 4];   // 32 KB
    __shared__ uint32_t sB[8 * 8 * 32 * 2];   // 16 KB

    const int kh = blockIdx.x;
    const int r0 = blockIdx.y * 128;
    const int tid = threadIdx.x;
    const int w = tid >> 5, lane = tid & 31;
    const int gp = lane >> 2, tgp = lane & 3;
    const int wr = (w >> 1) * 32, wc = (w & 1) * 32;
    const float* Dk = g_D + kh * 1024 * 64;
    const float* Ak = A + (size_t)kh * 1024 * 64;

    // staging address precompute (phase 1)
    const int row_b = tid >> 4;            // base row (step 16)
    const int c4 = (tid & 15) * 4;         // depth cols within chunk
    const int ksX = c4 >> 3, qX = (c4 >> 2) & 1, swX = ksX & 3;
    const int ksD_b = row_b;               // D k-row base

    float4 xr[8];
    float4 dr[4];

    // prefetch chunk 0
#pragma unroll
    for (int p = 0; p < 8; p++)
        xr[p] = *(const float4*)(x + (size_t)(r0 + row_b + p * 16) * 1024 + c4);
#pragma unroll
    for (int p = 0; p < 4; p++)
        dr[p] = *(const float4*)(Dk + (size_t)(ksD_b + p * 16) * 64 + c4);

    float acc[2][4][4];
#pragma unroll
    for (int mt = 0; mt < 2; mt++)
#pragma unroll
        for (int nt = 0; nt < 4; nt++)
#pragma unroll
            for (int i = 0; i < 4; i++) acc[mt][nt][i] = 0.f;

    // ---- Phase 1: u[128][64] = x_tile @ D ----
    for (int it = 0; it < 16; it++) {
        // store current chunk regs -> smem (tf32, frag-major)
#pragma unroll
        for (int p = 0; p < 8; p++) {
            int row = row_b + p * 16;
            int rt = row >> 4, h = (row >> 3) & 1, g = row & 7;
            int base = ((rt * 8 + ksX) * 32) * 4 + (qX * 2 + h);
            int l0 = g * 4;
            sA[base + (l0 + (0 ^ swX)) * 4] = f2tf(xr[p].x);
            sA[base + (l0 + (1 ^ swX)) * 4] = f2tf(xr[p].y);
            sA[base + (l0 + (2 ^ swX)) * 4] = f2tf(xr[p].z);
            sA[base + (l0 + (3 ^ swX)) * 4] = f2tf(xr[p].w);
        }
#pragma unroll
        for (int p = 0; p < 4; p++) {
            int rr = ksD_b + p * 16;
            int ks = rr >> 3, tg = rr & 3, q = (rr >> 2) & 1;
            float vv[4] = {dr[p].x, dr[p].y, dr[p].z, dr[p].w};
#pragma unroll
            for (int j = 0; j < 4; j++) {
                int col = c4 + j, ct = col >> 3, gc = col & 7;
                int lsw = (gc * 4 + tg) ^ (ks & 3);
                sB[((ct * 8 + ks) * 32 + lsw) * 2 + q] = f2tf(vv[j]);
            }
        }
        __syncthreads();

        // prefetch next chunk while computing this one
        if (it < 15) {
            int kc = (it + 1) * 64;
#pragma unroll
            for (int p = 0; p < 8; p++)
                xr[p] = *(const float4*)(x + (size_t)(r0 + row_b + p * 16) * 1024 + kc + c4);
#pragma unroll
            for (int p = 0; p < 4; p++)
                dr[p] = *(const float4*)(Dk + (size_t)(kc + ksD_b + p * 16) * 64 + c4);
        }

#pragma unroll
        for (int ks = 0; ks < 8; ks++) {
            int lsw = lane ^ (ks & 3);
            uint32_t a0[4], a1[4];
            *(uint4*)a0 = *(const uint4*)&sA[(((2 * (w >> 1)) * 8 + ks) * 32 + lsw) * 4];
            *(uint4*)a1 = *(const uint4*)&sA[(((2 * (w >> 1) + 1) * 8 + ks) * 32 + lsw) * 4];
#pragma unroll
            for (int nt = 0; nt < 4; nt++) {
                uint32_t b[2];
                *(uint2*)b = *(const uint2*)&sB[((((w & 1) * 4 + nt) * 8 + ks) * 32 + lsw) * 2];
                mma8(acc[0][nt], a0, b);
                mma8(acc[1][nt], a1, b);
            }
        }
        __syncthreads();
    }

    // ---- spill u to smem as phase-2 A operand (tf32, frag-major) ----
#pragma unroll
    for (int mt = 0; mt < 2; mt++) {
        int rt = 2 * (w >> 1) + mt;
#pragma unroll
        for (int nt = 0; nt < 4; nt++) {
            int ks2 = (w & 1) * 4 + nt;
            int sw = ks2 & 3;
#pragma unroll
            for (int i = 0; i < 4; i++) {
                int rcol = 2 * tgp + (i & 1);
                int lane2 = (gp * 4 + (rcol & 3)) ^ sw;
                int f = (rcol >> 2) * 2 + (i >> 1);
                sA[((rt * 8 + ks2) * 32 + lane2) * 4 + f] = f2tf(acc[mt][nt][i]);
            }
        }
    }
    __syncthreads();

    // ---- Phase 2: out_tile = u @ A^T, 16 e-tiles of 64, pipelined ----
    float4 ar[4];
#pragma unroll
    for (int p = 0; p < 4; p++)
        ar[p] = *(const float4*)(Ak + (size_t)(row_b + p * 16) * 64 + c4);

    for (int et = 0; et < 16; et++) {
        int e0 = et * 64;
        // store A regs -> sB
#pragma unroll
        for (int p = 0; p < 4; p++) {
            int er = row_b + p * 16;
            int ct = er >> 3, gc = er & 7;
            float vv[4] = {ar[p].x, ar[p].y, ar[p].z, ar[p].w};
#pragma unroll
            for (int j = 0; j < 4; j++) {
                int lsw = (gc * 4 + ((c4 + j) & 3)) ^ swX;   // tg = (c4+j)&3 ; c4%4==0
                sB[((ct * 8 + ksX) * 32 + ((gc * 4 + j) ^ swX)) * 2 + qX] = f2tf(vv[j]);
                (void)lsw;
            }
        }
        __syncthreads();

        if (et < 15) {
            size_t e0n = (size_t)(et + 1) * 64;
#pragma unroll
            for (int p = 0; p < 4; p++)
                ar[p] = *(const float4*)(Ak + (e0n + row_b + p * 16) * 64 + c4);
        }

        float o[2][4][4];
#pragma unroll
        for (int mt = 0; mt < 2; mt++)
#pragma unroll
            for (int nt = 0; nt < 4; nt++)
#pragma unroll
                for (int i = 0; i < 4; i++) o[mt][nt][i] = 0.f;

#pragma unroll
        for (int ks = 0; ks < 8; ks++) {
            int lsw = lane ^ (ks & 3);
            uint32_t a0[4], a1[4];
            *(uint4*)a0 = *(const uint4*)&sA[(((2 * (w >> 1)) * 8 + ks) * 32 + lsw) * 4];
            *(uint4*)a1 = *(const uint4*)&sA[(((2 * (w >> 1) + 1) * 8 + ks) * 32 + lsw) * 4];
#pragma unroll
            for (int nt = 0; nt < 4; nt++) {
                uint32_t b[2];
                *(uint2*)b = *(const uint2*)&sB[((((w & 1) * 4 + nt) * 8 + ks) * 32 + lsw) * 2];
                mma8(o[0][nt], a0, b);
                mma8(o[1][nt], a1, b);
            }
        }

#pragma unroll
        for (int mt = 0; mt < 2; mt++) {
            int row = r0 + wr + mt * 16 + gp;
#pragma unroll
            for (int nt = 0; nt < 4; nt++) {
                size_t col = (size_t)kh * 1024 + e0 + wc + nt * 8 + 2 * tgp;
                *(float2*)(out + (size_t)row * 3072 + col) =
                    make_float2(o[mt][nt][0], o[mt][nt][1]);
                *(float2*)(out + (size_t)(row + 8) * 3072 + col) =
                    make_float2(o[mt][nt][2], o[mt][nt][3]);
            }
        }
        __syncthreads();
    }
}

extern "C" void kernel_launch(void* const* d_in, const int* in_sizes, int n_in,
                              void* d_out, int out_size) {
    (void)in_sizes; (void)n_in; (void)out_size;
    const float* x  = (const float*)d_in[0];
    const float* Ws = (const float*)d_in[1];
    const float* A  = (const float*)d_in[2];
    const float* B  = (const float*)d_in[3];
    float* out = (float*)d_out;

    zero_k<<<576, 256>>>();
    t1_k<<<dim3(6, 12, 3), 256>>>(B, Ws);
    c_k<<<dim3(8, 3), 256>>>(B);
    d_k3<<<dim3(128, 3), 256>>>(A);
    fused_k<<<dim3(3, 128), 256>>>(x, A, out);
}

// round 6
// speedup vs baseline: 1.6539x; 1.1725x over previous
#include <cuda_runtime.h>
#include <cstdint>

#define NROW 16384

// Scratch (allocation-free: __device__ globals)
__device__ __align__(16) float    g_T1p[8 * 3 * 64 * 768];  // per-t-split B @ Ws^T
__device__ __align__(16) float    g_Cp [4 * 3 * 64 * 64];   // per-s-split T1 @ B^T
__device__ __align__(16) uint32_t g_Df [3 * 16 * 4096];     // D in tf32 frag-image per 64-chunk
__device__ __align__(16) uint32_t g_Af [3 * 16 * 4096];     // A in tf32 frag-image per etile

__device__ __forceinline__ uint32_t f2tf(float f) {
    uint32_t u;
    asm("cvt.rna.tf32.f32 %0, %1;" : "=r"(u) : "f"(f));
    return u;
}

__device__ __forceinline__ uint32_t smem_u32(const void* p) {
    uint32_t a;
    asm("{ .reg .u64 t; cvta.to.shared.u64 t, %1; cvt.u32.u64 %0, t; }" : "=r"(a) : "l"(p));
    return a;
}

__device__ __forceinline__ void mma8(float c[4], const uint32_t a[4], const uint32_t b[2]) {
    asm volatile(
        "mma.sync.aligned.m16n8k8.row.col.f32.tf32.tf32.f32 "
        "{%0,%1,%2,%3},{%4,%5,%6,%7},{%8,%9},{%0,%1,%2,%3};"
        : "+f"(c[0]), "+f"(c[1]), "+f"(c[2]), "+f"(c[3])
        : "r"(a[0]), "r"(a[1]), "r"(a[2]), "r"(a[3]), "r"(b[0]), "r"(b[1]));
}

#define CP_ASYNC16(dst, src) \
    asm volatile("cp.async.cg.shared.global [%0], [%1], 16;" :: "r"(dst), "l"(src) : "memory")
#define CP_COMMIT() asm volatile("cp.async.commit_group;" ::: "memory")
#define CP_WAIT0()  asm volatile("cp.async.wait_group 0;" ::: "memory")

// B-operand frag-image word index for element (n-row nr, k-col kc) in a 64x64 tile
__device__ __forceinline__ int bimg_idx(int nr, int kc) {
    int ct = nr >> 3, gc = nr & 7;
    int ks = kc >> 3, tg = kc & 3, q = (kc >> 2) & 1;
    return ((ct * 8 + ks) * 32 + ((gc * 4 + tg) ^ (ks & 3))) * 2 + q;
}

// ---------------- precompute (atomic-free) ----------------

// T1p[p][k][r][s] = sum_{t in split p} B[k,r,t] * Ws[k,s,t]
__global__ __launch_bounds__(256) void t1_k(const float* __restrict__ B,
                                            const float* __restrict__ Ws) {
    __shared__ float Bs[64][33];
    __shared__ float Wss[128][33];
    int k = blockIdx.z, s0 = blockIdx.x * 128, p = blockIdx.y;
    int t0 = p * 96;
    int tid = threadIdx.x;
    const float* Bk = B  + k * 64 * 768;
    const float* Wk = Ws + k * 768 * 768;

    float acc[4][8];
#pragma unroll
    for (int i = 0; i < 4; i++)
#pragma unroll
        for (int j = 0; j < 8; j++) acc[i][j] = 0.f;

    int rl = tid >> 4;
    int sl = tid & 15;

    for (int tc = 0; tc < 96; tc += 32) {
        int tb = t0 + tc;
        int c4 = (tid & 7) * 4;
#pragma unroll
        for (int pp = 0; pp < 2; pp++) {
            int r = (tid >> 3) + pp * 32;
            float4 v = *(const float4*)(Bk + r * 768 + tb + c4);
            Bs[r][c4] = v.x; Bs[r][c4 + 1] = v.y; Bs[r][c4 + 2] = v.z; Bs[r][c4 + 3] = v.w;
        }
#pragma unroll
        for (int pp = 0; pp < 4; pp++) {
            int s = (tid >> 3) + pp * 32;
            float4 v = *(const float4*)(Wk + (s0 + s) * 768 + tb + c4);
            Wss[s][c4] = v.x; Wss[s][c4 + 1] = v.y; Wss[s][c4 + 2] = v.z; Wss[s][c4 + 3] = v.w;
        }
        __syncthreads();
#pragma unroll 8
        for (int tt = 0; tt < 32; tt++) {
            float bv[4], wv[8];
#pragma unroll
            for (int i = 0; i < 4; i++) bv[i] = Bs[rl + 16 * i][tt];
#pragma unroll
            for (int j = 0; j < 8; j++) wv[j] = Wss[sl + 16 * j][tt];
#pragma unroll
            for (int i = 0; i < 4; i++)
#pragma unroll
                for (int j = 0; j < 8; j++) acc[i][j] += bv[i] * wv[j];
        }
        __syncthreads();
    }
#pragma unroll
    for (int i = 0; i < 4; i++)
#pragma unroll
        for (int j = 0; j < 8; j++)
            g_T1p[((size_t)((p * 3 + k) * 64 + rl + 16 * i)) * 768 + s0 + sl + 16 * j] = acc[i][j];
}

// Cp[sp][k][r][r2] = sum_{s in split sp} (sum_p T1p[p,k,r,s]) * B[k,r2,s]
__global__ __launch_bounds__(256) void c_k(const float* __restrict__ B) {
    __shared__ float T1s[64][33];
    __shared__ float Bs2[64][33];
    int k = blockIdx.y, sp = blockIdx.x;
    int sb0 = sp * 192;
    int tid = threadIdx.x;
    const float* Bk = B + k * 64 * 768;

    float acc[4][4];
#pragma unroll
    for (int i = 0; i < 4; i++)
#pragma unroll
        for (int j = 0; j < 4; j++) acc[i][j] = 0.f;

    int rl  = tid & 15;
    int r2l = tid >> 4;

    for (int sc = 0; sc < 192; sc += 32) {
        int sb = sb0 + sc;
        int c4 = (tid & 7) * 4;
#pragma unroll
        for (int pq = 0; pq < 2; pq++) {
            int r = (tid >> 3) + pq * 32;
            float4 s = make_float4(0.f, 0.f, 0.f, 0.f);
#pragma unroll
            for (int pp = 0; pp < 8; pp++) {
                float4 v = *(const float4*)(g_T1p + ((size_t)((pp * 3 + k) * 64 + r)) * 768 + sb + c4);
                s.x += v.x; s.y += v.y; s.z += v.z; s.w += v.w;
            }
            T1s[r][c4] = s.x; T1s[r][c4 + 1] = s.y; T1s[r][c4 + 2] = s.z; T1s[r][c4 + 3] = s.w;
            float4 w = *(const float4*)(Bk + r * 768 + sb + c4);
            Bs2[r][c4] = w.x; Bs2[r][c4 + 1] = w.y; Bs2[r][c4 + 2] = w.z; Bs2[r][c4 + 3] = w.w;
        }
        __syncthreads();
#pragma unroll 8
        for (int tt = 0; tt < 32; tt++) {
            float tv[4], bv[4];
#pragma unroll
            for (int i = 0; i < 4; i++) tv[i] = T1s[rl + 16 * i][tt];
#pragma unroll
            for (int j = 0; j < 4; j++) bv[j] = Bs2[r2l + 16 * j][tt];
#pragma unroll
            for (int i = 0; i < 4; i++)
#pragma unroll
                for (int j = 0; j < 4; j++) acc[i][j] += tv[i] * bv[j];
        }
        __syncthreads();
    }
#pragma unroll
    for (int i = 0; i < 4; i++)
#pragma unroll
        for (int j = 0; j < 4; j++)
            g_Cp[((sp * 3 + k) * 64 + rl + 16 * i) * 64 + r2l + 16 * j] = acc[i][j];
}

// D[k][d][r] = sum_rp A[k,d,rp]*C[k,rp,r]; write tf32 frag-image:
// chunk = d>>6 holds B-operand tile with k-dim = d&63, n-dim = r.
// grid (128 d-blocks of 8, 3 k), block 256
__global__ __launch_bounds__(256) void d_k(const float* __restrict__ A) {
    __shared__ float Cs[64][66];
    __shared__ float As[8][64];
    int k = blockIdx.y, d0 = blockIdx.x * 8;
    int tid = threadIdx.x;
    for (int idx = tid; idx < 4096; idx += 256) {
        float s = 0.f;
#pragma unroll
        for (int sp = 0; sp < 4; sp++) s += g_Cp[(sp * 3 + k) * 4096 + idx];
        Cs[idx >> 6][idx & 63] = s;
    }
    for (int idx = tid; idx < 512; idx += 256)
        As[idx >> 6][idx & 63] = A[(size_t)(k * 1024 + d0 + (idx >> 6)) * 64 + (idx & 63)];
    __syncthreads();
    int dl = tid >> 5, r = (tid & 31) * 2;
    float a0 = 0.f, a1 = 0.f;
#pragma unroll
    for (int rp = 0; rp < 64; rp++) {
        float av = As[dl][rp];
        float2 c = *(const float2*)&Cs[rp][r];
        a0 += av * c.x; a1 += av * c.y;
    }
    int d = d0 + dl;
    uint32_t* img = g_Df + ((size_t)k * 16 + (d >> 6)) * 4096;
    int rr = d & 63;
    img[bimg_idx(r, rr)]     = f2tf(a0);   // n-row = r (u col), k-col = rr (depth)
    img[bimg_idx(r + 1, rr)] = f2tf(a1);
}

// A frag-image per (k, etile): n-row = e within etile, k-col = r.
// grid (8 etiles, 3 k) x 2 launches, block 256
__global__ __launch_bounds__(256) void af_k(const float* __restrict__ A, int et0) {
    int k = blockIdx.y, et = et0 + blockIdx.x;
    int tid = threadIdx.x;
    uint32_t* img = g_Af + ((size_t)k * 16 + et) * 4096;
    const float* Ae = A + (size_t)(k * 1024 + et * 64) * 64;
    for (int t = tid; t < 4096; t += 256) {
        int er = t >> 6, r = t & 63;
        img[bimg_idx(er, r)] = f2tf(Ae[er * 64 + r]);
    }
}

// ---------------- fused main GEMM (mma.sync tf32, occ-4, cp.async B-operands) ----------------
// Phase 1: u[64,64] = x_tile @ D(kh). Phase 2: out_tile = u @ A(kh)^T over 16 etiles.
// block 128 (4 warps, 2x2 of 32x32 warp tiles), grid (3, 256), 48KB static smem.
__global__ __launch_bounds__(128, 4) void fused_k(const float* __restrict__ x,
                                                  float* __restrict__ out) {
    __shared__ uint32_t sA[4 * 8 * 32 * 4];      // 16KB: x-frag chunk, then u-frag
    __shared__ uint32_t sB[2][8 * 8 * 32 * 2];   // 2 x 16KB: D / A images

    const int tid = threadIdx.x;
    const int w = tid >> 5, lane = tid & 31;
    const int gp = lane >> 2, tgp = lane & 3;
    const int kh = blockIdx.x;
    const int r0 = blockIdx.y * 64;
    const int wr = (w >> 1) * 32, wc = (w & 1) * 32;

    const uint32_t* Df = g_Df + (size_t)kh * 16 * 4096;
    const uint32_t* Af = g_Af + (size_t)kh * 16 * 4096;

    const int rowb = tid >> 4;              // 0..7
    const int c4 = (tid & 15) * 4;
    const int ksX = c4 >> 3, qX = (c4 >> 2) & 1, swX = ksX & 3;

    const uint32_t sB0 = smem_u32(&sB[0][0]);
    const uint32_t sB1 = smem_u32(&sB[1][0]);

    // prologue: x chunk 0 regs + cp.async D chunk 0 -> sB[0]
    float4 xa[8];
#pragma unroll
    for (int p = 0; p < 8; p++)
        xa[p] = *(const float4*)(x + (size_t)(r0 + rowb + p * 8) * 1024 + c4);
#pragma unroll
    for (int p = 0; p < 8; p++)
        CP_ASYNC16(sB0 + (tid + p * 128) * 16, Df + (tid + p * 128) * 4);
    CP_COMMIT();

    float acc[2][4][4];
#pragma unroll
    for (int mt = 0; mt < 2; mt++)
#pragma unroll
        for (int nt = 0; nt < 4; nt++)
#pragma unroll
            for (int i = 0; i < 4; i++) acc[mt][nt][i] = 0.f;

    // ---- Phase 1: 16 chunks of 64 depth ----
    for (int ci = 0; ci < 16; ci++) {
        const int b = ci & 1;
        // STS x chunk (tf32, frag-major)
#pragma unroll
        for (int p = 0; p < 8; p++) {
            int row = rowb + p * 8;
            int rt = row >> 4, h = (row >> 3) & 1, g = row & 7;
            int base = ((rt * 8 + ksX) * 32) * 4 + (qX * 2 + h);
            int l0 = g * 4;
            sA[base + (l0 + (0 ^ swX)) * 4] = f2tf(xa[p].x);
            sA[base + (l0 + (1 ^ swX)) * 4] = f2tf(xa[p].y);
            sA[base + (l0 + (2 ^ swX)) * 4] = f2tf(xa[p].z);
            sA[base + (l0 + (3 ^ swX)) * 4] = f2tf(xa[p].w);
        }
        CP_WAIT0();
        __syncthreads();

        // prefetch next chunk: x -> regs, D -> other buffer via cp.async
        if (ci < 15) {
            int kc = (ci + 1) * 64;
#pragma unroll
            for (int p = 0; p < 8; p++)
                xa[p] = *(const float4*)(x + (size_t)(r0 + rowb + p * 8) * 1024 + kc + c4);
            const uint32_t dst = b ? sB0 : sB1;
            const uint32_t* srcD = Df + (size_t)(ci + 1) * 4096;
#pragma unroll
            for (int p = 0; p < 8; p++)
                CP_ASYNC16(dst + (tid + p * 128) * 16, srcD + (tid + p * 128) * 4);
            CP_COMMIT();
        }

        const uint32_t* Bp = sB[b];
#pragma unroll
        for (int ks = 0; ks < 8; ks++) {
            int lsw = lane ^ (ks & 3);
            uint32_t a0[4], a1[4];
            *(uint4*)a0 = *(const uint4*)&sA[(((2 * (w >> 1)) * 8 + ks) * 32 + lsw) * 4];
            *(uint4*)a1 = *(const uint4*)&sA[(((2 * (w >> 1) + 1) * 8 + ks) * 32 + lsw) * 4];
#pragma unroll
            for (int nt = 0; nt < 4; nt++) {
                uint32_t bb[2];
                *(uint2*)bb = *(const uint2*)&Bp[((((w & 1) * 4 + nt) * 8 + ks) * 32 + lsw) * 2];
                mma8(acc[0][nt], a0, bb);
                mma8(acc[1][nt], a1, bb);
            }
        }
        __syncthreads();
    }

    // ---- spill u to sA as phase-2 A operand (tf32, frag-major) ----
#pragma unroll
    for (int mt = 0; mt < 2; mt++) {
        int rt = 2 * (w >> 1) + mt;
#pragma unroll
        for (int nt = 0; nt < 4; nt++) {
            int ks2 = (w & 1) * 4 + nt;
            int sw = ks2 & 3;
#pragma unroll
            for (int i = 0; i < 4; i++) {
                int rcol = 2 * tgp + (i & 1);
                int lane2 = (gp * 4 + (rcol & 3)) ^ sw;
                int f = (rcol >> 2) * 2 + (i >> 1);
                sA[((rt * 8 + ks2) * 32 + lane2) * 4 + f] = f2tf(acc[mt][nt][i]);
            }
        }
    }
    // issue A etile 0 while spilling settles
#pragma unroll
    for (int p = 0; p < 8; p++)
        CP_ASYNC16(sB0 + (tid + p * 128) * 16, Af + (tid + p * 128) * 4);
    CP_COMMIT();
    __syncthreads();

    // ---- Phase 2: 16 etiles of 64 ----
    for (int et = 0; et < 16; et++) {
        const int b = et & 1;
        CP_WAIT0();
        __syncthreads();
        if (et < 15) {
            const uint32_t dst = b ? sB0 : sB1;
            const uint32_t* srcA = Af + (size_t)(et + 1) * 4096;
#pragma unroll
            for (int p = 0; p < 8; p++)
                CP_ASYNC16(dst + (tid + p * 128) * 16, srcA + (tid + p * 128) * 4);
            CP_COMMIT();
        }

        float o[2][4][4];
#pragma unroll
        for (int mt = 0; mt < 2; mt++)
#pragma unroll
            for (int nt = 0; nt < 4; nt++)
#pragma unroll
                for (int i = 0; i < 4; i++) o[mt][nt][i] = 0.f;

        const uint32_t* Bp = sB[b];
#pragma unroll
        for (int ks = 0; ks < 8; ks++) {
            int lsw = lane ^ (ks & 3);
            uint32_t a0[4], a1[4];
            *(uint4*)a0 = *(const uint4*)&sA[(((2 * (w >> 1)) * 8 + ks) * 32 + lsw) * 4];
            *(uint4*)a1 = *(const uint4*)&sA[(((2 * (w >> 1) + 1) * 8 + ks) * 32 + lsw) * 4];
#pragma unroll
            for (int nt = 0; nt < 4; nt++) {
                uint32_t bb[2];
                *(uint2*)bb = *(const uint2*)&Bp[((((w & 1) * 4 + nt) * 8 + ks) * 32 + lsw) * 2];
                mma8(o[0][nt], a0, bb);
                mma8(o[1][nt], a1, bb);
            }
        }

#pragma unroll
        for (int mt = 0; mt < 2; mt++) {
            int row = r0 + wr + mt * 16 + gp;
#pragma unroll
            for (int nt = 0; nt < 4; nt++) {
                size_t col = (size_t)kh * 1024 + et * 64 + wc + nt * 8 + 2 * tgp;
                *(float2*)(out + (size_t)row * 3072 + col) =
                    make_float2(o[mt][nt][0], o[mt][nt][1]);
                *(float2*)(out + (size_t)(row + 8) * 3072 + col) =
                    make_float2(o[mt][nt][2], o[mt][nt][3]);
            }
        }
    }
}

extern "C" void kernel_launch(void* const* d_in, const int* in_sizes, int n_in,
                              void* d_out, int out_size) {
    (void)in_sizes; (void)n_in; (void)out_size;
    const float* x  = (const float*)d_in[0];
    const float* Ws = (const float*)d_in[1];
    const float* A  = (const float*)d_in[2];
    const float* B  = (const float*)d_in[3];
    float* out = (float*)d_out;

    // 5 launches before fused_k so ncu (-s 5 -c 1) profiles fused_k
    t1_k<<<dim3(6, 8, 3), 256>>>(B, Ws);
    c_k<<<dim3(4, 3), 256>>>(B);
    d_k<<<dim3(128, 3), 256>>>(A);
    af_k<<<dim3(8, 3), 256>>>(A, 0);
    af_k<<<dim3(8, 3), 256>>>(A, 8);
    fused_k<<<dim3(3, 256), 128>>>(x, out);
}

// round 7
// speedup vs baseline: 1.7788x; 1.0755x over previous
#include <cuda_runtime.h>
#include <cstdint>

#define NROW 16384

// Scratch (allocation-free: __device__ globals)
__device__ __align__(16) float    g_T1p[8 * 3 * 64 * 768];  // per-t-split B @ Ws^T
__device__ __align__(16) float    g_Cp [4 * 3 * 64 * 64];   // per-s-split T1 @ B^T
__device__ __align__(16) uint32_t g_Df [3 * 16 * 4096];     // D in tf32 frag-image per 64-chunk
__device__ __align__(16) uint32_t g_Af [3 * 16 * 4096];     // A in tf32 frag-image per etile

__device__ __forceinline__ uint32_t f2tf(float f) {
    uint32_t u;
    asm("cvt.rna.tf32.f32 %0, %1;" : "=r"(u) : "f"(f));
    return u;
}

__device__ __forceinline__ uint32_t smem_u32(const void* p) {
    uint32_t a;
    asm("{ .reg .u64 t; cvta.to.shared.u64 t, %1; cvt.u32.u64 %0, t; }" : "=r"(a) : "l"(p));
    return a;
}

__device__ __forceinline__ void mma8(float c[4], const uint32_t a[4], const uint32_t b[2]) {
    asm volatile(
        "mma.sync.aligned.m16n8k8.row.col.f32.tf32.tf32.f32 "
        "{%0,%1,%2,%3},{%4,%5,%6,%7},{%8,%9},{%0,%1,%2,%3};"
        : "+f"(c[0]), "+f"(c[1]), "+f"(c[2]), "+f"(c[3])
        : "r"(a[0]), "r"(a[1]), "r"(a[2]), "r"(a[3]), "r"(b[0]), "r"(b[1]));
}

#define CP_ASYNC16(dst, src) \
    asm volatile("cp.async.cg.shared.global [%0], [%1], 16;" :: "r"(dst), "l"(src) : "memory")
#define CP_COMMIT() asm volatile("cp.async.commit_group;" ::: "memory")
#define CP_WAIT0()  asm volatile("cp.async.wait_group 0;" ::: "memory")

// B-operand frag-image word index for element (n-row nr, k-col kc) in a 64x64 tile
__device__ __forceinline__ int bimg_idx(int nr, int kc) {
    int ct = nr >> 3, gc = nr & 7;
    int ks = kc >> 3, tg = kc & 3, q = (kc >> 2) & 1;
    return ((ct * 8 + ks) * 32 + ((gc * 4 + tg) ^ (ks & 3))) * 2 + q;
}

// ---------------- precompute (atomic-free) ----------------

// T1p[p][k][r][s] = sum_{t in split p} B[k,r,t] * Ws[k,s,t]
__global__ __launch_bounds__(256) void t1_k(const float* __restrict__ B,
                                            const float* __restrict__ Ws) {
    __shared__ float Bs[64][33];
    __shared__ float Wss[128][33];
    int k = blockIdx.z, s0 = blockIdx.x * 128, p = blockIdx.y;
    int t0 = p * 96;
    int tid = threadIdx.x;
    const float* Bk = B  + k * 64 * 768;
    const float* Wk = Ws + k * 768 * 768;

    float acc[4][8];
#pragma unroll
    for (int i = 0; i < 4; i++)
#pragma unroll
        for (int j = 0; j < 8; j++) acc[i][j] = 0.f;

    int rl = tid >> 4;
    int sl = tid & 15;

    for (int tc = 0; tc < 96; tc += 32) {
        int tb = t0 + tc;
        int c4 = (tid & 7) * 4;
#pragma unroll
        for (int pp = 0; pp < 2; pp++) {
            int r = (tid >> 3) + pp * 32;
            float4 v = *(const float4*)(Bk + r * 768 + tb + c4);
            Bs[r][c4] = v.x; Bs[r][c4 + 1] = v.y; Bs[r][c4 + 2] = v.z; Bs[r][c4 + 3] = v.w;
        }
#pragma unroll
        for (int pp = 0; pp < 4; pp++) {
            int s = (tid >> 3) + pp * 32;
            float4 v = *(const float4*)(Wk + (s0 + s) * 768 + tb + c4);
            Wss[s][c4] = v.x; Wss[s][c4 + 1] = v.y; Wss[s][c4 + 2] = v.z; Wss[s][c4 + 3] = v.w;
        }
        __syncthreads();
#pragma unroll 8
        for (int tt = 0; tt < 32; tt++) {
            float bv[4], wv[8];
#pragma unroll
            for (int i = 0; i < 4; i++) bv[i] = Bs[rl + 16 * i][tt];
#pragma unroll
            for (int j = 0; j < 8; j++) wv[j] = Wss[sl + 16 * j][tt];
#pragma unroll
            for (int i = 0; i < 4; i++)
#pragma unroll
                for (int j = 0; j < 8; j++) acc[i][j] += bv[i] * wv[j];
        }
        __syncthreads();
    }
#pragma unroll
    for (int i = 0; i < 4; i++)
#pragma unroll
        for (int j = 0; j < 8; j++)
            g_T1p[((size_t)((p * 3 + k) * 64 + rl + 16 * i)) * 768 + s0 + sl + 16 * j] = acc[i][j];
}

// Cp[sp][k][r][r2] = sum_{s in split sp} (sum_p T1p[p,k,r,s]) * B[k,r2,s]
__global__ __launch_bounds__(256) void c_k(const float* __restrict__ B) {
    __shared__ float T1s[64][33];
    __shared__ float Bs2[64][33];
    int k = blockIdx.y, sp = blockIdx.x;
    int sb0 = sp * 192;
    int tid = threadIdx.x;
    const float* Bk = B + k * 64 * 768;

    float acc[4][4];
#pragma unroll
    for (int i = 0; i < 4; i++)
#pragma unroll
        for (int j = 0; j < 4; j++) acc[i][j] = 0.f;

    int rl  = tid & 15;
    int r2l = tid >> 4;

    for (int sc = 0; sc < 192; sc += 32) {
        int sb = sb0 + sc;
        int c4 = (tid & 7) * 4;
#pragma unroll
        for (int pq = 0; pq < 2; pq++) {
            int r = (tid >> 3) + pq * 32;
            float4 s = make_float4(0.f, 0.f, 0.f, 0.f);
#pragma unroll
            for (int pp = 0; pp < 8; pp++) {
                float4 v = *(const float4*)(g_T1p + ((size_t)((pp * 3 + k) * 64 + r)) * 768 + sb + c4);
                s.x += v.x; s.y += v.y; s.z += v.z; s.w += v.w;
            }
            T1s[r][c4] = s.x; T1s[r][c4 + 1] = s.y; T1s[r][c4 + 2] = s.z; T1s[r][c4 + 3] = s.w;
            float4 w = *(const float4*)(Bk + r * 768 + sb + c4);
            Bs2[r][c4] = w.x; Bs2[r][c4 + 1] = w.y; Bs2[r][c4 + 2] = w.z; Bs2[r][c4 + 3] = w.w;
        }
        __syncthreads();
#pragma unroll 8
        for (int tt = 0; tt < 32; tt++) {
            float tv[4], bv[4];
#pragma unroll
            for (int i = 0; i < 4; i++) tv[i] = T1s[rl + 16 * i][tt];
#pragma unroll
            for (int j = 0; j < 4; j++) bv[j] = Bs2[r2l + 16 * j][tt];
#pragma unroll
            for (int i = 0; i < 4; i++)
#pragma unroll
                for (int j = 0; j < 4; j++) acc[i][j] += tv[i] * bv[j];
        }
        __syncthreads();
    }
#pragma unroll
    for (int i = 0; i < 4; i++)
#pragma unroll
        for (int j = 0; j < 4; j++)
            g_Cp[((sp * 3 + k) * 64 + rl + 16 * i) * 64 + r2l + 16 * j] = acc[i][j];
}

// Combined kernel, grid (192, 3), block 256:
//  blocks x <  128: D[k][d][r] = sum_rp A[k,d,rp]*C[k,rp,r] -> g_Df frag-image
//  blocks x >= 128: gather-build g_Af frag-image from A (4 words / thread, STG.128)
__global__ __launch_bounds__(256) void d_k(const float* __restrict__ A) {
    int k = blockIdx.y;
    if (blockIdx.x >= 128) {
        // ---- A frag-image build (gather-4) ----
        int xb = blockIdx.x - 128;                    // 0..63
        int widx = xb * 1024 + threadIdx.x * 4;       // word offset within this k (0..65535)
        int et   = widx >> 12;
        int base = widx & 4095;
        const float* Ae = A + (size_t)(k * 1024 + et * 64) * 64;
        int ks = (base >> 6) & 7, ct = base >> 9, sw = ks & 3;
        int L  = (base >> 1) & 31;                    // even
        uint32_t w4[4];
#pragma unroll
        for (int j = 0; j < 4; j++) {
            int lsw = L + (j >> 1);
            int q   = j & 1;
            int g   = lsw ^ sw;
            int nr  = ct * 8 + (g >> 2);
            int kc  = ks * 8 + q * 4 + (g & 3);
            w4[j] = f2tf(Ae[nr * 64 + kc]);
        }
        *(uint4*)&g_Af[((size_t)k * 16 + et) * 4096 + base] =
            make_uint4(w4[0], w4[1], w4[2], w4[3]);
        return;
    }

    // ---- D compute + frag-image store ----
    __shared__ float Cs[64][66];
    __shared__ float As[8][64];
    int d0 = blockIdx.x * 8;
    int tid = threadIdx.x;
    for (int idx = tid; idx < 4096; idx += 256) {
        float s = 0.f;
#pragma unroll
        for (int sp = 0; sp < 4; sp++) s += g_Cp[(sp * 3 + k) * 4096 + idx];
        Cs[idx >> 6][idx & 63] = s;
    }
    for (int idx = tid; idx < 512; idx += 256)
        As[idx >> 6][idx & 63] = A[(size_t)(k * 1024 + d0 + (idx >> 6)) * 64 + (idx & 63)];
    __syncthreads();
    int dl = tid >> 5, r = (tid & 31) * 2;
    float a0 = 0.f, a1 = 0.f;
#pragma unroll
    for (int rp = 0; rp < 64; rp++) {
        float av = As[dl][rp];
        float2 c = *(const float2*)&Cs[rp][r];
        a0 += av * c.x; a1 += av * c.y;
    }
    int d = d0 + dl;
    uint32_t* img = g_Df + ((size_t)k * 16 + (d >> 6)) * 4096;
    int rr = d & 63;
    img[bimg_idx(r, rr)]     = f2tf(a0);   // n-row = r (u col), k-col = rr (depth)
    img[bimg_idx(r + 1, rr)] = f2tf(a1);
}

// ---------------- fused main GEMM (mma.sync tf32, occ-4, cp.async B-operands) ----------------
// Phase 1: u[64,64] = x_tile @ D(kh). Phase 2: out_tile = u @ A(kh)^T over 16 etiles.
// block 128 (4 warps, 2x2 of 32x32 warp tiles), grid (3, 256), 48KB static smem.
__global__ __launch_bounds__(128, 4) void fused_k(const float* __restrict__ x,
                                                  float* __restrict__ out) {
    __shared__ uint32_t sA[4 * 8 * 32 * 4];      // 16KB: x-frag chunk, then u-frag
    __shared__ uint32_t sB[2][8 * 8 * 32 * 2];   // 2 x 16KB: D / A images

    const int tid = threadIdx.x;
    const int w = tid >> 5, lane = tid & 31;
    const int gp = lane >> 2, tgp = lane & 3;
    const int kh = blockIdx.x;
    const int r0 = blockIdx.y * 64;
    const int wr = (w >> 1) * 32, wc = (w & 1) * 32;

    const uint32_t* Df = g_Df + (size_t)kh * 16 * 4096;
    const uint32_t* Af = g_Af + (size_t)kh * 16 * 4096;

    const int rowb = tid >> 4;              // 0..7
    const int c4 = (tid & 15) * 4;
    const int ksX = c4 >> 3, qX = (c4 >> 2) & 1, swX = ksX & 3;

    const uint32_t sB0 = smem_u32(&sB[0][0]);
    const uint32_t sB1 = smem_u32(&sB[1][0]);

    // prologue: x chunk 0 regs + cp.async D chunk 0 -> sB[0]
    float4 xa[8];
#pragma unroll
    for (int p = 0; p < 8; p++)
        xa[p] = *(const float4*)(x + (size_t)(r0 + rowb + p * 8) * 1024 + c4);
#pragma unroll
    for (int p = 0; p < 8; p++)
        CP_ASYNC16(sB0 + (tid + p * 128) * 16, Df + (tid + p * 128) * 4);
    CP_COMMIT();

    float acc[2][4][4];
#pragma unroll
    for (int mt = 0; mt < 2; mt++)
#pragma unroll
        for (int nt = 0; nt < 4; nt++)
#pragma unroll
            for (int i = 0; i < 4; i++) acc[mt][nt][i] = 0.f;

    // ---- Phase 1: 16 chunks of 64 depth ----
    for (int ci = 0; ci < 16; ci++) {
        const int b = ci & 1;
        // STS x chunk (tf32, frag-major)
#pragma unroll
        for (int p = 0; p < 8; p++) {
            int row = rowb + p * 8;
            int rt = row >> 4, h = (row >> 3) & 1, g = row & 7;
            int base = ((rt * 8 + ksX) * 32) * 4 + (qX * 2 + h);
            int l0 = g * 4;
            sA[base + (l0 + (0 ^ swX)) * 4] = f2tf(xa[p].x);
            sA[base + (l0 + (1 ^ swX)) * 4] = f2tf(xa[p].y);
            sA[base + (l0 + (2 ^ swX)) * 4] = f2tf(xa[p].z);
            sA[base + (l0 + (3 ^ swX)) * 4] = f2tf(xa[p].w);
        }
        CP_WAIT0();
        __syncthreads();

        // prefetch next chunk: x -> regs, D -> other buffer via cp.async
        if (ci < 15) {
            int kc = (ci + 1) * 64;
#pragma unroll
            for (int p = 0; p < 8; p++)
                xa[p] = *(const float4*)(x + (size_t)(r0 + rowb + p * 8) * 1024 + kc + c4);
            const uint32_t dst = b ? sB0 : sB1;
            const uint32_t* srcD = Df + (size_t)(ci + 1) * 4096;
#pragma unroll
            for (int p = 0; p < 8; p++)
                CP_ASYNC16(dst + (tid + p * 128) * 16, srcD + (tid + p * 128) * 4);
            CP_COMMIT();
        }

        const uint32_t* Bp = sB[b];
#pragma unroll
        for (int ks = 0; ks < 8; ks++) {
            int lsw = lane ^ (ks & 3);
            uint32_t a0[4], a1[4];
            *(uint4*)a0 = *(const uint4*)&sA[(((2 * (w >> 1)) * 8 + ks) * 32 + lsw) * 4];
            *(uint4*)a1 = *(const uint4*)&sA[(((2 * (w >> 1) + 1) * 8 + ks) * 32 + lsw) * 4];
#pragma unroll
            for (int nt = 0; nt < 4; nt++) {
                uint32_t bb[2];
                *(uint2*)bb = *(const uint2*)&Bp[((((w & 1) * 4 + nt) * 8 + ks) * 32 + lsw) * 2];
                mma8(acc[0][nt], a0, bb);
                mma8(acc[1][nt], a1, bb);
            }
        }
        __syncthreads();
    }

    // ---- spill u to sA as phase-2 A operand (tf32, frag-major) ----
#pragma unroll
    for (int mt = 0; mt < 2; mt++) {
        int rt = 2 * (w >> 1) + mt;
#pragma unroll
        for (int nt = 0; nt < 4; nt++) {
            int ks2 = (w & 1) * 4 + nt;
            int sw = ks2 & 3;
#pragma unroll
            for (int i = 0; i < 4; i++) {
                int rcol = 2 * tgp + (i & 1);
                int lane2 = (gp * 4 + (rcol & 3)) ^ sw;
                int f = (rcol >> 2) * 2 + (i >> 1);
                sA[((rt * 8 + ks2) * 32 + lane2) * 4 + f] = f2tf(acc[mt][nt][i]);
            }
        }
    }
    // issue A etile 0 while spilling settles
#pragma unroll
    for (int p = 0; p < 8; p++)
        CP_ASYNC16(sB0 + (tid + p * 128) * 16, Af + (tid + p * 128) * 4);
    CP_COMMIT();
    __syncthreads();

    // ---- Phase 2: 16 etiles of 64 ----
    for (int et = 0; et < 16; et++) {
        const int b = et & 1;
        CP_WAIT0();
        __syncthreads();
        if (et < 15) {
            const uint32_t dst = b ? sB0 : sB1;
            const uint32_t* srcA = Af + (size_t)(et + 1) * 4096;
#pragma unroll
            for (int p = 0; p < 8; p++)
                CP_ASYNC16(dst + (tid + p * 128) * 16, srcA + (tid + p * 128) * 4);
            CP_COMMIT();
        }

        float o[2][4][4];
#pragma unroll
        for (int mt = 0; mt < 2; mt++)
#pragma unroll
            for (int nt = 0; nt < 4; nt++)
#pragma unroll
                for (int i = 0; i < 4; i++) o[mt][nt][i] = 0.f;

        const uint32_t* Bp = sB[b];
#pragma unroll
        for (int ks = 0; ks < 8; ks++) {
            int lsw = lane ^ (ks & 3);
            uint32_t a0[4], a1[4];
            *(uint4*)a0 = *(const uint4*)&sA[(((2 * (w >> 1)) * 8 + ks) * 32 + lsw) * 4];
            *(uint4*)a1 = *(const uint4*)&sA[(((2 * (w >> 1) + 1) * 8 + ks) * 32 + lsw) * 4];
#pragma unroll
            for (int nt = 0; nt < 4; nt++) {
                uint32_t bb[2];
                *(uint2*)bb = *(const uint2*)&Bp[((((w & 1) * 4 + nt) * 8 + ks) * 32 + lsw) * 2];
                mma8(o[0][nt], a0, bb);
                mma8(o[1][nt], a1, bb);
            }
        }

#pragma unroll
        for (int mt = 0; mt < 2; mt++) {
            int row = r0 + wr + mt * 16 + gp;
#pragma unroll
            for (int nt = 0; nt < 4; nt++) {
                size_t col = (size_t)kh * 1024 + et * 64 + wc + nt * 8 + 2 * tgp;
                *(float2*)(out + (size_t)row * 3072 + col) =
                    make_float2(o[mt][nt][0], o[mt][nt][1]);
                *(float2*)(out + (size_t)(row + 8) * 3072 + col) =
                    make_float2(o[mt][nt][2], o[mt][nt][3]);
            }
        }
    }
}

extern "C" void kernel_launch(void* const* d_in, const int* in_sizes, int n_in,
                              void* d_out, int out_size) {
    (void)in_sizes; (void)n_in; (void)out_size;
    const float* x  = (const float*)d_in[0];
    const float* Ws = (const float*)d_in[1];
    const float* A  = (const float*)d_in[2];
    const float* B  = (const float*)d_in[3];
    float* out = (float*)d_out;

    // fused_k is the 4th launch (ncu profiles launch #4)
    t1_k<<<dim3(6, 8, 3), 256>>>(B, Ws);
    c_k<<<dim3(4, 3), 256>>>(B);
    d_k<<<dim3(192, 3), 256>>>(A);
    fused_k<<<dim3(3, 256), 128>>>(x, out);
}

// round 8
// speedup vs baseline: 1.8438x; 1.0366x over previous
#include <cuda_runtime.h>
#include <cstdint>

#define NROW 16384

// Scratch (allocation-free: __device__ globals)
__device__ __align__(16) float    g_T1p[8 * 3 * 64 * 768];  // per-t-split B @ Ws^T
__device__ __align__(16) float    g_Cp [4 * 3 * 64 * 64];   // per-s-split T1 @ B^T
__device__ __align__(16) uint32_t g_Df [3 * 16 * 4096];     // D in tf32 frag-image per 64-chunk
__device__ __align__(16) uint32_t g_Af [3 * 16 * 4096];     // A in tf32 frag-image per etile

__device__ __forceinline__ uint32_t f2tf(float f) {
    uint32_t u;
    asm("cvt.rna.tf32.f32 %0, %1;" : "=r"(u) : "f"(f));
    return u;
}

__device__ __forceinline__ uint32_t smem_u32(const void* p) {
    uint32_t a;
    asm("{ .reg .u64 t; cvta.to.shared.u64 t, %1; cvt.u32.u64 %0, t; }" : "=r"(a) : "l"(p));
    return a;
}

__device__ __forceinline__ void mma8(float c[4], const uint32_t a[4], const uint32_t b[2]) {
    asm volatile(
        "mma.sync.aligned.m16n8k8.row.col.f32.tf32.tf32.f32 "
        "{%0,%1,%2,%3},{%4,%5,%6,%7},{%8,%9},{%0,%1,%2,%3};"
        : "+f"(c[0]), "+f"(c[1]), "+f"(c[2]), "+f"(c[3])
        : "r"(a[0]), "r"(a[1]), "r"(a[2]), "r"(a[3]), "r"(b[0]), "r"(b[1]));
}

#define CP_ASYNC16(dst, src) \
    asm volatile("cp.async.cg.shared.global [%0], [%1], 16;" :: "r"(dst), "l"(src) : "memory")
#define CP_COMMIT() asm volatile("cp.async.commit_group;" ::: "memory")
#define CP_WAIT0()  asm volatile("cp.async.wait_group 0;" ::: "memory")

// B-operand frag-image word index for element (n-row nr, k-col kc) in a 64x64 tile
__device__ __forceinline__ int bimg_idx(int nr, int kc) {
    int ct = nr >> 3, gc = nr & 7;
    int ks = kc >> 3, tg = kc & 3, q = (kc >> 2) & 1;
    return ((ct * 8 + ks) * 32 + ((gc * 4 + tg) ^ (ks & 3))) * 2 + q;
}

// ---------------- precompute (atomic-free) ----------------

// T1p[p][k][r][s] = sum_{t in split p} B[k,r,t] * Ws[k,s,t]
__global__ __launch_bounds__(256) void t1_k(const float* __restrict__ B,
                                            const float* __restrict__ Ws) {
    __shared__ float Bs[64][33];
    __shared__ float Wss[128][33];
    int k = blockIdx.z, s0 = blockIdx.x * 128, p = blockIdx.y;
    int t0 = p * 96;
    int tid = threadIdx.x;
    const float* Bk = B  + k * 64 * 768;
    const float* Wk = Ws + k * 768 * 768;

    float acc[4][8];
#pragma unroll
    for (int i = 0; i < 4; i++)
#pragma unroll
        for (int j = 0; j < 8; j++) acc[i][j] = 0.f;

    int rl = tid >> 4;
    int sl = tid & 15;

    for (int tc = 0; tc < 96; tc += 32) {
        int tb = t0 + tc;
        int c4 = (tid & 7) * 4;
#pragma unroll
        for (int pp = 0; pp < 2; pp++) {
            int r = (tid >> 3) + pp * 32;
            float4 v = *(const float4*)(Bk + r * 768 + tb + c4);
            Bs[r][c4] = v.x; Bs[r][c4 + 1] = v.y; Bs[r][c4 + 2] = v.z; Bs[r][c4 + 3] = v.w;
        }
#pragma unroll
        for (int pp = 0; pp < 4; pp++) {
            int s = (tid >> 3) + pp * 32;
            float4 v = *(const float4*)(Wk + (s0 + s) * 768 + tb + c4);
            Wss[s][c4] = v.x; Wss[s][c4 + 1] = v.y; Wss[s][c4 + 2] = v.z; Wss[s][c4 + 3] = v.w;
        }
        __syncthreads();
#pragma unroll 8
        for (int tt = 0; tt < 32; tt++) {
            float bv[4], wv[8];
#pragma unroll
            for (int i = 0; i < 4; i++) bv[i] = Bs[rl + 16 * i][tt];
#pragma unroll
            for (int j = 0; j < 8; j++) wv[j] = Wss[sl + 16 * j][tt];
#pragma unroll
            for (int i = 0; i < 4; i++)
#pragma unroll
                for (int j = 0; j < 8; j++) acc[i][j] += bv[i] * wv[j];
        }
        __syncthreads();
    }
#pragma unroll
    for (int i = 0; i < 4; i++)
#pragma unroll
        for (int j = 0; j < 8; j++)
            g_T1p[((size_t)((p * 3 + k) * 64 + rl + 16 * i)) * 768 + s0 + sl + 16 * j] = acc[i][j];
}

// Cp[sp][k][r][r2] = sum_{s in split sp} (sum_p T1p[p,k,r,s]) * B[k,r2,s]
__global__ __launch_bounds__(256) void c_k(const float* __restrict__ B) {
    __shared__ float T1s[64][33];
    __shared__ float Bs2[64][33];
    int k = blockIdx.y, sp = blockIdx.x;
    int sb0 = sp * 192;
    int tid = threadIdx.x;
    const float* Bk = B + k * 64 * 768;

    float acc[4][4];
#pragma unroll
    for (int i = 0; i < 4; i++)
#pragma unroll
        for (int j = 0; j < 4; j++) acc[i][j] = 0.f;

    int rl  = tid & 15;
    int r2l = tid >> 4;

    for (int sc = 0; sc < 192; sc += 32) {
        int sb = sb0 + sc;
        int c4 = (tid & 7) * 4;
#pragma unroll
        for (int pq = 0; pq < 2; pq++) {
            int r = (tid >> 3) + pq * 32;
            float4 s = make_float4(0.f, 0.f, 0.f, 0.f);
#pragma unroll
            for (int pp = 0; pp < 8; pp++) {
                float4 v = *(const float4*)(g_T1p + ((size_t)((pp * 3 + k) * 64 + r)) * 768 + sb + c4);
                s.x += v.x; s.y += v.y; s.z += v.z; s.w += v.w;
            }
            T1s[r][c4] = s.x; T1s[r][c4 + 1] = s.y; T1s[r][c4 + 2] = s.z; T1s[r][c4 + 3] = s.w;
            float4 w = *(const float4*)(Bk + r * 768 + sb + c4);
            Bs2[r][c4] = w.x; Bs2[r][c4 + 1] = w.y; Bs2[r][c4 + 2] = w.z; Bs2[r][c4 + 3] = w.w;
        }
        __syncthreads();
#pragma unroll 8
        for (int tt = 0; tt < 32; tt++) {
            float tv[4], bv[4];
#pragma unroll
            for (int i = 0; i < 4; i++) tv[i] = T1s[rl + 16 * i][tt];
#pragma unroll
            for (int j = 0; j < 4; j++) bv[j] = Bs2[r2l + 16 * j][tt];
#pragma unroll
            for (int i = 0; i < 4; i++)
#pragma unroll
                for (int j = 0; j < 4; j++) acc[i][j] += tv[i] * bv[j];
        }
        __syncthreads();
    }
#pragma unroll
    for (int i = 0; i < 4; i++)
#pragma unroll
        for (int j = 0; j < 4; j++)
            g_Cp[((sp * 3 + k) * 64 + rl + 16 * i) * 64 + r2l + 16 * j] = acc[i][j];
}

// Combined kernel, grid (192, 3), block 256:
//  blocks x <  128: D[k][d][r] = sum_rp A[k,d,rp]*C[k,rp,r] -> g_Df frag-image
//  blocks x >= 128: gather-build g_Af frag-image from A (4 words / thread, STG.128)
__global__ __launch_bounds__(256) void d_k(const float* __restrict__ A) {
    int k = blockIdx.y;
    if (blockIdx.x >= 128) {
        int xb = blockIdx.x - 128;                    // 0..63
        int widx = xb * 1024 + threadIdx.x * 4;       // word offset within this k
        int et   = widx >> 12;
        int base = widx & 4095;
        const float* Ae = A + (size_t)(k * 1024 + et * 64) * 64;
        int ks = (base >> 6) & 7, ct = base >> 9, sw = ks & 3;
        int L  = (base >> 1) & 31;                    // even
        uint32_t w4[4];
#pragma unroll
        for (int j = 0; j < 4; j++) {
            int lsw = L + (j >> 1);
            int q   = j & 1;
            int g   = lsw ^ sw;
            int nr  = ct * 8 + (g >> 2);
            int kc  = ks * 8 + q * 4 + (g & 3);
            w4[j] = f2tf(Ae[nr * 64 + kc]);
        }
        *(uint4*)&g_Af[((size_t)k * 16 + et) * 4096 + base] =
            make_uint4(w4[0], w4[1], w4[2], w4[3]);
        return;
    }

    __shared__ float Cs[64][66];
    __shared__ float As[8][64];
    int d0 = blockIdx.x * 8;
    int tid = threadIdx.x;
    for (int idx = tid; idx < 4096; idx += 256) {
        float s = 0.f;
#pragma unroll
        for (int sp = 0; sp < 4; sp++) s += g_Cp[(sp * 3 + k) * 4096 + idx];
        Cs[idx >> 6][idx & 63] = s;
    }
    for (int idx = tid; idx < 512; idx += 256)
        As[idx >> 6][idx & 63] = A[(size_t)(k * 1024 + d0 + (idx >> 6)) * 64 + (idx & 63)];
    __syncthreads();
    int dl = tid >> 5, r = (tid & 31) * 2;
    float a0 = 0.f, a1 = 0.f;
#pragma unroll
    for (int rp = 0; rp < 64; rp++) {
        float av = As[dl][rp];
        float2 c = *(const float2*)&Cs[rp][r];
        a0 += av * c.x; a1 += av * c.y;
    }
    int d = d0 + dl;
    uint32_t* img = g_Df + ((size_t)k * 16 + (d >> 6)) * 4096;
    int rr = d & 63;
    img[bimg_idx(r, rr)]     = f2tf(a0);
    img[bimg_idx(r + 1, rr)] = f2tf(a1);
}

// ---------------- fused main GEMM (mma.sync tf32, occ-4, cp.async B-operands) ----------------
// Phase 1: u[64,64] = x_tile @ D(kh). Phase 2: out_tile = u @ A(kh)^T over 16 etiles,
// with u-fragments held in registers (no smem A-operand traffic in phase 2).
// block 128 (4 warps, 2x2 of 32x32 warp tiles), grid (3, 256), 48KB static smem.
__global__ __launch_bounds__(128, 4) void fused_k(const float* __restrict__ x,
                                                  float* __restrict__ out) {
    __shared__ uint32_t sA[4 * 8 * 32 * 4];      // 16KB: x-frag chunk, then u-frag
    __shared__ uint32_t sB[2][8 * 8 * 32 * 2];   // 2 x 16KB: D / A images

    const int tid = threadIdx.x;
    const int w = tid >> 5, lane = tid & 31;
    const int gp = lane >> 2, tgp = lane & 3;
    const int kh = blockIdx.x;
    const int r0 = blockIdx.y * 64;
    const int wr = (w >> 1) * 32, wc = (w & 1) * 32;

    const uint32_t* Df = g_Df + (size_t)kh * 16 * 4096;
    const uint32_t* Af = g_Af + (size_t)kh * 16 * 4096;

    const int rowb = tid >> 4;              // 0..7 (g)
    const int c4 = (tid & 15) * 4;
    const int ksX = c4 >> 3, qX = (c4 >> 2) & 1, swX = ksX & 3;

    const uint32_t sB0 = smem_u32(&sB[0][0]);
    const uint32_t sB1 = smem_u32(&sB[1][0]);

    // prologue: x chunk 0 regs + cp.async D chunk 0 -> sB[0]
    float4 xa[8];
#pragma unroll
    for (int p = 0; p < 8; p++)
        xa[p] = *(const float4*)(x + (size_t)(r0 + rowb + p * 8) * 1024 + c4);
#pragma unroll
    for (int p = 0; p < 8; p++)
        CP_ASYNC16(sB0 + (tid + p * 128) * 16, Df + (tid + p * 128) * 4);
    CP_COMMIT();

    float acc[2][4][4];
#pragma unroll
    for (int mt = 0; mt < 2; mt++)
#pragma unroll
        for (int nt = 0; nt < 4; nt++)
#pragma unroll
            for (int i = 0; i < 4; i++) acc[mt][nt][i] = 0.f;

    // ---- Phase 1: 16 chunks of 64 depth ----
    for (int ci = 0; ci < 16; ci++) {
        const int b = ci & 1;
        // STS x chunk (tf32, frag-major) — paired rows (h=0/1) -> STS.64
        // xa[p]: row = rowb + p*8 -> rt = p>>1, h = p&1; f = qX*2 + h adjacent words.
#pragma unroll
        for (int rt = 0; rt < 4; rt++) {
            int base = ((rt * 8 + ksX) * 32) * 4 + qX * 2;
            int l0 = rowb * 4;
            float4 v0 = xa[2 * rt], v1 = xa[2 * rt + 1];
            float e0[4] = {v0.x, v0.y, v0.z, v0.w};
            float e1[4] = {v1.x, v1.y, v1.z, v1.w};
#pragma unroll
            for (int j = 0; j < 4; j++) {
                uint32_t addr = smem_u32(&sA[base + (l0 + (j ^ swX)) * 4]);
                asm volatile("st.shared.v2.b32 [%0], {%1,%2};"
                             :: "r"(addr), "r"(f2tf(e0[j])), "r"(f2tf(e1[j])) : "memory");
            }
        }
        CP_WAIT0();
        __syncthreads();

        // prefetch next chunk: x -> regs, D -> other buffer via cp.async
        if (ci < 15) {
            int kc = (ci + 1) * 64;
#pragma unroll
            for (int p = 0; p < 8; p++)
                xa[p] = *(const float4*)(x + (size_t)(r0 + rowb + p * 8) * 1024 + kc + c4);
            const uint32_t dst = b ? sB0 : sB1;
            const uint32_t* srcD = Df + (size_t)(ci + 1) * 4096;
#pragma unroll
            for (int p = 0; p < 8; p++)
                CP_ASYNC16(dst + (tid + p * 128) * 16, srcD + (tid + p * 128) * 4);
            CP_COMMIT();
        }

        const uint32_t* Bp = sB[b];
#pragma unroll
        for (int ks = 0; ks < 8; ks++) {
            int lsw = lane ^ (ks & 3);
            uint32_t a0[4], a1[4];
            *(uint4*)a0 = *(const uint4*)&sA[(((2 * (w >> 1)) * 8 + ks) * 32 + lsw) * 4];
            *(uint4*)a1 = *(const uint4*)&sA[(((2 * (w >> 1) + 1) * 8 + ks) * 32 + lsw) * 4];
#pragma unroll
            for (int nt = 0; nt < 4; nt++) {
                uint32_t bb[2];
                *(uint2*)bb = *(const uint2*)&Bp[((((w & 1) * 4 + nt) * 8 + ks) * 32 + lsw) * 2];
                mma8(acc[0][nt], a0, bb);
                mma8(acc[1][nt], a1, bb);
            }
        }
        __syncthreads();
    }

    // ---- spill u to sA as phase-2 A operand (tf32, frag-major) ----
#pragma unroll
    for (int mt = 0; mt < 2; mt++) {
        int rt = 2 * (w >> 1) + mt;
#pragma unroll
        for (int nt = 0; nt < 4; nt++) {
            int ks2 = (w & 1) * 4 + nt;
            int sw = ks2 & 3;
#pragma unroll
            for (int i = 0; i < 4; i++) {
                int rcol = 2 * tgp + (i & 1);
                int lane2 = (gp * 4 + (rcol & 3)) ^ sw;
                int f = (rcol >> 2) * 2 + (i >> 1);
                sA[((rt * 8 + ks2) * 32 + lane2) * 4 + f] = f2tf(acc[mt][nt][i]);
            }
        }
    }
    // issue A etile 0 while spilling settles
#pragma unroll
    for (int p = 0; p < 8; p++)
        CP_ASYNC16(sB0 + (tid + p * 128) * 16, Af + (tid + p * 128) * 4);
    CP_COMMIT();
    __syncthreads();

    // load u-fragments ONCE into registers (phase-2 A operand)
    uint32_t uf[2][8][4];
#pragma unroll
    for (int ks = 0; ks < 8; ks++) {
        int lsw = lane ^ (ks & 3);
        *(uint4*)uf[0][ks] = *(const uint4*)&sA[(((2 * (w >> 1)) * 8 + ks) * 32 + lsw) * 4];
        *(uint4*)uf[1][ks] = *(const uint4*)&sA[(((2 * (w >> 1) + 1) * 8 + ks) * 32 + lsw) * 4];
    }

    // ---- Phase 2: 16 etiles of 64 ----
    for (int et = 0; et < 16; et++) {
        const int b = et & 1;
        CP_WAIT0();
        __syncthreads();
        if (et < 15) {
            const uint32_t dst = b ? sB0 : sB1;
            const uint32_t* srcA = Af + (size_t)(et + 1) * 4096;
#pragma unroll
            for (int p = 0; p < 8; p++)
                CP_ASYNC16(dst + (tid + p * 128) * 16, srcA + (tid + p * 128) * 4);
            CP_COMMIT();
        }

        float o[2][4][4];
#pragma unroll
        for (int mt = 0; mt < 2; mt++)
#pragma unroll
            for (int nt = 0; nt < 4; nt++)
#pragma unroll
                for (int i = 0; i < 4; i++) o[mt][nt][i] = 0.f;

        const uint32_t* Bp = sB[b];
#pragma unroll
        for (int ks = 0; ks < 8; ks++) {
            int lsw = lane ^ (ks & 3);
#pragma unroll
            for (int nt = 0; nt < 4; nt++) {
                uint32_t bb[2];
                *(uint2*)bb = *(const uint2*)&Bp[((((w & 1) * 4 + nt) * 8 + ks) * 32 + lsw) * 2];
                mma8(o[0][nt], uf[0][ks], bb);
                mma8(o[1][nt], uf[1][ks], bb);
            }
        }

#pragma unroll
        for (int mt = 0; mt < 2; mt++) {
            int row = r0 + wr + mt * 16 + gp;
#pragma unroll
            for (int nt = 0; nt < 4; nt++) {
                size_t col = (size_t)kh * 1024 + et * 64 + wc + nt * 8 + 2 * tgp;
                *(float2*)(out + (size_t)row * 3072 + col) =
                    make_float2(o[mt][nt][0], o[mt][nt][1]);
                *(float2*)(out + (size_t)(row + 8) * 3072 + col) =
                    make_float2(o[mt][nt][2], o[mt][nt][3]);
            }
        }
    }
}

extern "C" void kernel_launch(void* const* d_in, const int* in_sizes, int n_in,
                              void* d_out, int out_size) {
    (void)in_sizes; (void)n_in; (void)out_size;
    const float* x  = (const float*)d_in[0];
    const float* Ws = (const float*)d_in[1];
    const float* A  = (const float*)d_in[2];
    const float* B  = (const float*)d_in[3];
    float* out = (float*)d_out;

    // fused_k is the 4th launch (ncu profiles launch #4)
    t1_k<<<dim3(6, 8, 3), 256>>>(B, Ws);
    c_k<<<dim3(4, 3), 256>>>(B);
    d_k<<<dim3(192, 3), 256>>>(A);
    fused_k<<<dim3(3, 256), 128>>>(x, out);
}